// round 5
// baseline (speedup 1.0000x reference)
#include <cuda_runtime.h>
#include <math.h>

#define PI_F 3.14159265358979323846f

#define Bb   2
#define Cc   128
#define Hh   128
#define Ww   256
#define HW   32768          // Hh*Ww
#define AUXC 133
#define KWF  129            // rfft width bins

typedef unsigned long long ull;

// ---------------- packed fp32x2 helpers ----------------------------------
__device__ __forceinline__ ull pk2(float lo, float hi) {
    ull r;
    asm("mov.b64 %0, {%1,%2};" : "=l"(r) : "f"(lo), "f"(hi));
    return r;
}
__device__ __forceinline__ void fma2(ull& d, ull a, ull b) {
    asm("fma.rn.f32x2 %0, %1, %2, %0;" : "+l"(d) : "l"(a), "l"(b));
}
__device__ __forceinline__ float2 up2(ull v) {
    float2 f;
    asm("mov.b64 {%0,%1}, %2;" : "=f"(f.x), "=f"(f.y) : "l"(v));
    return f;
}

// ---------------- static scratch (no allocations allowed) ----------------
__device__ float2 g_R[Bb*KWF*Cc*Hh];      // row-FFT result, layout [b][kw][c][m]
__device__ float  g_part[Bb*KWF*64*128];  // per-channel-pair |FFT| partials
__device__ float  g_feh[Bb*Hh*KWF];       // |FFT| channel-mean, [b][kh][kw]
__device__ float  g_fe[Bb*HW];            // resized freq energy [b][h][w]
__device__ float  g_aux[Bb*AUXC*HW];      // concat(x, coord4, fe)
__device__ float  g_off[Bb*18*HW];        // offset conv output
__device__ float  g_gbuf[Bb*66*HW];       // gate hidden
__device__ float  g_gate[Bb*HW];          // sigmoid gate
__device__ float  g_ybase[Bb*Cc*HW];      // base conv output
__device__ float  g_xT[Bb*HW*Cc];         // x in NHWC for vector gathers
__device__ float  g_wP[9*Cc*Cc];          // def_w permuted to [kk*128+ci][co]

// ---------------- FFT over W (256-pt, real input, keep bins 0..128) ------
__global__ void fft_rows_k(const float* __restrict__ x) {
    __shared__ float2 sm[256];
    __shared__ float2 tw[128];
    int bid = blockIdx.x;
    int m = bid & (Hh-1);
    int c = (bid >> 7) & (Cc-1);
    int b = bid >> 14;
    int tid = threadIdx.x;
    float ang = -2.0f * PI_F * (float)tid / 256.0f;
    tw[tid] = make_float2(cosf(ang), sinf(ang));
    const float* row = x + ((size_t)(b*Cc + c)*Hh + m)*Ww;
    for (int i = tid; i < 256; i += 128) {
        int r = __brev(i) >> 24;
        sm[r] = make_float2(row[i], 0.0f);
    }
    __syncthreads();
#pragma unroll
    for (int s = 1; s <= 8; s++) {
        int half = 1 << (s-1);
        int pos = tid & (half-1);
        int i0 = ((tid >> (s-1)) << s) | pos;
        int i1 = i0 + half;
        float2 w = tw[pos << (8-s)];
        float2 a = sm[i0], bv = sm[i1];
        float2 t = make_float2(bv.x*w.x - bv.y*w.y, bv.x*w.y + bv.y*w.x);
        sm[i0] = make_float2(a.x + t.x, a.y + t.y);
        sm[i1] = make_float2(a.x - t.x, a.y - t.y);
        __syncthreads();
    }
    g_R[((size_t)(b*KWF + tid)*Cc + c)*Hh + m] = sm[tid];
    if (tid == 0)
        g_R[((size_t)(b*KWF + 128)*Cc + c)*Hh + m] = sm[128];
}

// ---------------- FFT over H: one block per (b,kw,channel-pair) ----------
__global__ void fft_cols_k(void) {
    __shared__ float2 sm[2][128];
    __shared__ float2 tw[64];
    __shared__ float  mg[128];
    int bid = blockIdx.x;
    int cp = bid & 63;
    int kw = (bid >> 6) % KWF;
    int b  = bid / (64*KWF);
    int tid = threadIdx.x;
    int lane = tid & 63;
    int f = tid >> 6;
    int c = cp*2 + f;
    if (tid < 64) {
        float ang = -2.0f * PI_F * (float)tid / 128.0f;
        tw[tid] = make_float2(cosf(ang), sinf(ang));
    }
    const float2* base = g_R + (size_t)(b*KWF + kw)*Cc*Hh + c*Hh;
#pragma unroll
    for (int i = lane; i < 128; i += 64) {
        sm[f][__brev(i) >> 25] = base[i];
    }
    __syncthreads();
#pragma unroll
    for (int s = 1; s <= 7; s++) {
        int half = 1 << (s-1);
        int pos = lane & (half-1);
        int i0 = ((lane >> (s-1)) << s) | pos;
        int i1 = i0 + half;
        float2 w = tw[pos << (7-s)];
        float2 a = sm[f][i0], bv = sm[f][i1];
        float2 t = make_float2(bv.x*w.x - bv.y*w.y, bv.x*w.y + bv.y*w.x);
        sm[f][i0] = make_float2(a.x + t.x, a.y + t.y);
        sm[f][i1] = make_float2(a.x - t.x, a.y - t.y);
        __syncthreads();
    }
    if (f == 0) {
#pragma unroll
        for (int i = lane; i < 128; i += 64) {
            float2 X = sm[0][i];
            mg[i] = sqrtf(X.x*X.x + X.y*X.y);
        }
    }
    __syncthreads();
    if (f == 1) {
#pragma unroll
        for (int i = lane; i < 128; i += 64) {
            float2 X = sm[1][i];
            g_part[(size_t)bid*128 + i] = mg[i] + sqrtf(X.x*X.x + X.y*X.y);
        }
    }
}

// ---------------- reduce 64 channel-pair partials -> g_feh ---------------
__global__ void reduce_feh_k(void) {
    int bid = blockIdx.x;           // b*KWF + kw
    int kw = bid % KWF;
    int b  = bid / KWF;
    int kh = threadIdx.x;
    float s = 0.0f;
    const float* p = g_part + (size_t)bid*64*128 + kh;
#pragma unroll 8
    for (int cp = 0; cp < 64; cp++)
        s += p[cp*128];
    float scale = 1.0f / (128.0f * sqrtf((float)(Hh*Ww)));
    g_feh[(size_t)(b*Hh + kh)*KWF + kw] = s * scale;
}

// ---------------- bilinear width resize 129 -> 256 (half-pixel, clamp) ---
__global__ void resize_fe_k(void) {
    int idx = blockIdx.x*blockDim.x + threadIdx.x;
    if (idx >= Bb*HW) return;
    int w = idx & (Ww-1);
    int h = (idx >> 8) & (Hh-1);
    int b = idx >> 15;
    float px = ((float)w + 0.5f) * (129.0f/256.0f) - 0.5f;
    float x0f = floorf(px);
    float f = px - x0f;
    int x0 = (int)x0f;
    int x1 = x0 + 1;
    x0 = min(max(x0, 0), 128);
    x1 = min(max(x1, 0), 128);
    const float* r = g_feh + (size_t)(b*Hh + h)*KWF;
    g_fe[idx] = r[x0]*(1.0f-f) + r[x1]*f;
}

// ---------------- aux = concat(x, sin/cos coords, fe) --------------------
__global__ void build_aux_k(const float* __restrict__ x) {
    int idx = blockIdx.x*blockDim.x + threadIdx.x;
    if (idx >= Bb*AUXC*HW) return;
    int w  = idx & (Ww-1);
    int h  = (idx >> 8) & (Hh-1);
    int ci = (idx / HW) % AUXC;
    int b  = idx / (AUXC*HW);
    float v;
    if (ci < Cc) {
        v = x[((size_t)(b*Cc + ci)*Hh + h)*Ww + w];
    } else if (ci == Cc) {
        float th = -PI_F + (2.0f*PI_F/255.0f)*(float)w; v = sinf(th);
    } else if (ci == Cc+1) {
        float th = -PI_F + (2.0f*PI_F/255.0f)*(float)w; v = cosf(th);
    } else if (ci == Cc+2) {
        float ph = -0.5f*PI_F + (PI_F/127.0f)*(float)h; v = sinf(ph);
    } else if (ci == Cc+3) {
        float ph = -0.5f*PI_F + (PI_F/127.0f)*(float)h; v = cosf(ph);
    } else {
        v = g_fe[(size_t)b*HW + h*Ww + w];
    }
    g_aux[idx] = v;
}

// ---------------- NCHW -> NHWC transpose of x ----------------------------
__global__ void transpose_k(const float* __restrict__ x) {
    __shared__ float t[32][33];
    int b  = blockIdx.z;
    int p0 = blockIdx.x * 32;   // hw
    int c0 = blockIdx.y * 32;   // channel
    int tx = threadIdx.x, ty = threadIdx.y;
#pragma unroll
    for (int j = 0; j < 4; j++)
        t[ty + j*8][tx] = x[(size_t)(b*Cc + c0 + ty + j*8)*HW + p0 + tx];
    __syncthreads();
#pragma unroll
    for (int j = 0; j < 4; j++)
        g_xT[(size_t)(b*HW + p0 + ty + j*8)*Cc + c0 + tx] = t[tx][ty + j*8];
}

// ---------------- def_w (co,ci,kk) -> wP[kk*128+ci][co] ------------------
__global__ void permw_k(const float* __restrict__ dw) {
    int idx = blockIdx.x*blockDim.x + threadIdx.x;
    if (idx >= 9*Cc*Cc) return;
    int co = idx & 127;
    int ci = (idx >> 7) & 127;
    int kk = idx >> 14;
    g_wP[idx] = dw[(size_t)(co*Cc + ci)*9 + kk];
}

// ---------------- direct 3x3 conv, pad 1, NCHW, f32x2 --------------------
// block: 32 couts x (32w x 8h) pixels; thread: 4 couts x 8 rows (4 y-pairs)
// IN_SEL: 0 = g_aux, 1 = external pointer (x)
// OUT_SEL: 0 = g_off, 1 = g_gbuf, 2 = g_ybase
template<int IN_SEL, int OUT_SEL, int CIN, int COUT, int RELU>
__global__ void __launch_bounds__(256) conv3x3_t(
        const float* __restrict__ xin, const float* __restrict__ wgt,
        const float* __restrict__ bias) {
    const float* in = (IN_SEL == 0) ? g_aux : xin;
    float* out = (OUT_SEL == 0) ? g_off : (OUT_SEL == 1) ? g_gbuf : g_ybase;
    __shared__ float tile[10][34];
    __shared__ ull   ws2[32][9];
    int tid = threadIdx.x;
    int xt = tid & 31;
    int ct = tid >> 5;                  // 0..7
    int x0 = blockIdx.x * 32;
    int y0 = blockIdx.y * 8;
    const int nCoBlk = (COUT + 31) >> 5;
    int b   = blockIdx.z / nCoBlk;
    int coB = (blockIdx.z % nCoBlk) * 32;
    ull acc[4][4];
#pragma unroll
    for (int j = 0; j < 4; j++)
#pragma unroll
        for (int yp = 0; yp < 4; yp++) acc[j][yp] = 0ULL;

    for (int ci = 0; ci < CIN; ci++) {
        const float* ip = in + (size_t)(b*CIN + ci)*HW;
#pragma unroll
        for (int i = tid; i < 340; i += 256) {
            int r = i / 34, cc = i % 34;
            int gy = y0 + r - 1, gx = x0 + cc - 1;
            float v = 0.0f;
            if (gy >= 0 && gy < Hh && gx >= 0 && gx < Ww) v = ip[gy*Ww + gx];
            tile[r][cc] = v;
        }
#pragma unroll
        for (int i = tid; i < 288; i += 256) {
            int co = i / 9, tap = i % 9;
            int gco = coB + co;
            float w = (gco < COUT) ? wgt[(size_t)(gco*CIN + ci)*9 + tap] : 0.0f;
            ws2[co][tap] = pk2(w, w);
        }
        __syncthreads();
        // packed row pairs vp[r] = (tile[r], tile[r+1]) at cols xt..xt+2
        ull vp[9][3];
        {
            float pr0 = tile[0][xt], pr1 = tile[0][xt+1], pr2 = tile[0][xt+2];
#pragma unroll
            for (int r = 1; r < 10; r++) {
                float c0v = tile[r][xt], c1v = tile[r][xt+1], c2v = tile[r][xt+2];
                vp[r-1][0] = pk2(pr0, c0v);
                vp[r-1][1] = pk2(pr1, c1v);
                vp[r-1][2] = pk2(pr2, c2v);
                pr0 = c0v; pr1 = c1v; pr2 = c2v;
            }
        }
#pragma unroll
        for (int j = 0; j < 4; j++) {
            int co = ct*4 + j;
            ull wr2[9];
#pragma unroll
            for (int t = 0; t < 9; t++) wr2[t] = ws2[co][t];
#pragma unroll
            for (int yp = 0; yp < 4; yp++) {
                ull s = acc[j][yp];
#pragma unroll
                for (int t = 0; t < 9; t++) {
                    int r = t / 3, k = t % 3;
                    fma2(s, vp[yp*2 + r][k], wr2[t]);
                }
                acc[j][yp] = s;
            }
        }
        __syncthreads();
    }
#pragma unroll
    for (int j = 0; j < 4; j++) {
        int co = coB + ct*4 + j;
        if (co < COUT) {
            float bs = bias[co];
            float* op = out + (size_t)(b*COUT + co)*HW + (size_t)y0*Ww + x0 + xt;
#pragma unroll
            for (int yp = 0; yp < 4; yp++) {
                float2 o = up2(acc[j][yp]);
                o.x += bs; o.y += bs;
                if (RELU) { o.x = fmaxf(o.x, 0.0f); o.y = fmaxf(o.y, 0.0f); }
                op[(yp*2    )*Ww] = o.x;
                op[(yp*2 + 1)*Ww] = o.y;
            }
        }
    }
}

// ---------------- 1x1 gate conv + sigmoid --------------------------------
__global__ void gate1x1_k(const float* __restrict__ w2, const float* __restrict__ b2) {
    int idx = blockIdx.x*blockDim.x + threadIdx.x;
    if (idx >= Bb*HW) return;
    int b = idx >> 15;
    int p = idx & (HW-1);
    float s = b2[0];
#pragma unroll 6
    for (int c = 0; c < 66; c++)
        s = fmaf(g_gbuf[(size_t)(b*66 + c)*HW + p], w2[c], s);
    g_gate[idx] = 1.0f / (1.0f + expf(-s));
}

// ---------------- fused deform-sample + 1x1 (K=1152 GEMM) + blend --------
// block: 128 couts x 128 pixels; thread: 8x8 register tile, f32x2 math
__global__ void __launch_bounds__(256) deform_gemm_k(
        const float* __restrict__ defb, float* __restrict__ out) {
    __shared__ __align__(16) float Ssm[32][128];
    __shared__ __align__(16) float Wsm[32][128];
    __shared__ int   mX0[128], mY0[128];
    __shared__ float mFx[128], mFy[128];
    int tid = threadIdx.x;
    int blk = blockIdx.x;
    int b    = blk >> 8;                 // 256 pixel-blocks per batch
    int pix0 = (blk & 255) * 128;
    int coIdx = (tid & 15) * 8;
    int pxIdx = (tid >> 4) * 8;
    ull acc[8][4];
#pragma unroll
    for (int i = 0; i < 8; i++)
#pragma unroll
        for (int j = 0; j < 4; j++) acc[i][j] = 0ULL;
    int p = tid >> 1, sub = tid & 1;

#pragma unroll 1
    for (int kk = 0; kk < 9; kk++) {
        __syncthreads();
        if (tid < 128) {
            int pp = pix0 + tid;
            int hh = pp >> 8, ww = pp & (Ww-1);
            float ox = g_off[(size_t)(b*18 + 2*kk    )*HW + pp];
            float oy = g_off[(size_t)(b*18 + 2*kk + 1)*HW + pp];
            float fpx = (float)ww + ox;
            float fpy = (float)hh + oy;
            float fx0 = floorf(fpx), fy0 = floorf(fpy);
            mX0[tid] = (int)fx0;  mY0[tid] = (int)fy0;
            mFx[tid] = fpx - fx0; mFy[tid] = fpy - fy0;
        }
        __syncthreads();
        int X0 = mX0[p], Y0 = mY0[p];
        float fx = mFx[p], fy = mFy[p];
        float w00 = (1.0f-fx)*(1.0f-fy), w10 = fx*(1.0f-fy);
        float w01 = (1.0f-fx)*fy,        w11 = fx*fy;
        if (X0   < 0 || X0   >= Ww) { w00 = 0.0f; w01 = 0.0f; }
        if (X0+1 < 0 || X0+1 >= Ww) { w10 = 0.0f; w11 = 0.0f; }
        if (Y0   < 0 || Y0   >= Hh) { w00 = 0.0f; w10 = 0.0f; }
        if (Y0+1 < 0 || Y0+1 >= Hh) { w01 = 0.0f; w11 = 0.0f; }
        ull w00p = pk2(w00, w00), w10p = pk2(w10, w10);
        ull w01p = pk2(w01, w01), w11p = pk2(w11, w11);
        int cx0 = min(max(X0,   0), Ww-1), cx1 = min(max(X0+1, 0), Ww-1);
        int cy0 = min(max(Y0,   0), Hh-1), cy1 = min(max(Y0+1, 0), Hh-1);
        const ulonglong2* p00 = (const ulonglong2*)(g_xT + ((size_t)(b*Hh + cy0)*Ww + cx0)*Cc);
        const ulonglong2* p10 = (const ulonglong2*)(g_xT + ((size_t)(b*Hh + cy0)*Ww + cx1)*Cc);
        const ulonglong2* p01 = (const ulonglong2*)(g_xT + ((size_t)(b*Hh + cy1)*Ww + cx0)*Cc);
        const ulonglong2* p11 = (const ulonglong2*)(g_xT + ((size_t)(b*Hh + cy1)*Ww + cx1)*Cc);

#pragma unroll 1
        for (int cc = 0; cc < 4; cc++) {
            __syncthreads();
            int cb  = sub * 16;             // within-chunk ci
            int cig = cc*32 + cb;           // global ci
#pragma unroll
            for (int q = 0; q < 4; q++) {
                int f4 = (cig >> 2) + q;
                ulonglong2 a00 = p00[f4], a10 = p10[f4], a01 = p01[f4], a11 = p11[f4];
                ull r01 = 0ULL, r23 = 0ULL;
                fma2(r01, w00p, a00.x); fma2(r01, w10p, a10.x);
                fma2(r01, w01p, a01.x); fma2(r01, w11p, a11.x);
                fma2(r23, w00p, a00.y); fma2(r23, w10p, a10.y);
                fma2(r23, w01p, a01.y); fma2(r23, w11p, a11.y);
                float2 f01 = up2(r01), f23 = up2(r23);
                Ssm[cb + q*4 + 0][p] = f01.x;
                Ssm[cb + q*4 + 1][p] = f01.y;
                Ssm[cb + q*4 + 2][p] = f23.x;
                Ssm[cb + q*4 + 3][p] = f23.y;
            }
            int krow0 = kk*128 + cc*32;
            {
                const float4* wsrc = (const float4*)(g_wP + (size_t)krow0*Cc);
                float4* wdst = (float4*)&Wsm[0][0];
#pragma unroll
                for (int i = tid; i < 1024; i += 256)
                    wdst[i] = wsrc[i];
            }
            __syncthreads();
#pragma unroll 8
            for (int kq = 0; kq < 32; kq++) {
                float4 a0 = *(const float4*)&Wsm[kq][coIdx];
                float4 a1 = *(const float4*)&Wsm[kq][coIdx+4];
                ulonglong2 bq0 = *(const ulonglong2*)&Ssm[kq][pxIdx];
                ulonglong2 bq1 = *(const ulonglong2*)&Ssm[kq][pxIdx+4];
                ull bv[4] = {bq0.x, bq0.y, bq1.x, bq1.y};
                float av[8] = {a0.x,a0.y,a0.z,a0.w,a1.x,a1.y,a1.z,a1.w};
#pragma unroll
                for (int i = 0; i < 8; i++) {
                    ull ap = pk2(av[i], av[i]);
#pragma unroll
                    for (int j = 0; j < 4; j++)
                        fma2(acc[i][j], ap, bv[j]);
                }
            }
        }
    }
    // epilogue: out = (1-gate)*y_base + gate*(y_def + bias)
    int pixg = pix0 + pxIdx;
    float gt[8];
#pragma unroll
    for (int j = 0; j < 8; j++) gt[j] = g_gate[(size_t)b*HW + pixg + j];
#pragma unroll
    for (int i = 0; i < 8; i++) {
        int co = coIdx + i;
        float bs = defb[co];
        const float* yb = g_ybase + (size_t)(b*Cc + co)*HW + pixg;
        float* op = out + (size_t)(b*Cc + co)*HW + pixg;
#pragma unroll
        for (int j4 = 0; j4 < 4; j4++) {
            float2 yd = up2(acc[i][j4]);
            int j0 = j4*2, j1 = j4*2 + 1;
            float y0v = yd.x + bs, y1v = yd.y + bs;
            op[j0] = (1.0f - gt[j0])*yb[j0] + gt[j0]*y0v;
            op[j1] = (1.0f - gt[j1])*yb[j1] + gt[j1]*y1v;
        }
    }
}

// ---------------- host launcher ------------------------------------------
extern "C" void kernel_launch(void* const* d_in, const int* in_sizes, int n_in,
                              void* d_out, int out_size) {
    const float* x      = (const float*)d_in[0];
    const float* off_w  = (const float*)d_in[1];
    const float* off_b  = (const float*)d_in[2];
    const float* gw1    = (const float*)d_in[3];
    const float* gb1    = (const float*)d_in[4];
    const float* gw2    = (const float*)d_in[5];
    const float* gb2    = (const float*)d_in[6];
    const float* base_w = (const float*)d_in[7];
    const float* base_b = (const float*)d_in[8];
    const float* def_w  = (const float*)d_in[9];
    const float* def_b  = (const float*)d_in[10];
    float* out = (float*)d_out;

    fft_rows_k<<<Bb*Cc*Hh, 128>>>(x);
    fft_cols_k<<<Bb*KWF*64, 128>>>();
    reduce_feh_k<<<Bb*KWF, 128>>>();
    resize_fe_k<<<(Bb*HW + 255)/256, 256>>>();
    build_aux_k<<<(Bb*AUXC*HW + 255)/256, 256>>>(x);
    transpose_k<<<dim3(HW/32, Cc/32, Bb), dim3(32, 8)>>>(x);
    permw_k<<<(9*Cc*Cc + 255)/256, 256>>>(def_w);

    conv3x3_t<0, 0, AUXC, 18, 0><<<dim3(8, 16, Bb*1), 256>>>(nullptr, off_w, off_b);
    conv3x3_t<0, 1, AUXC, 66, 1><<<dim3(8, 16, Bb*3), 256>>>(nullptr, gw1, gb1);
    conv3x3_t<1, 2, Cc,  Cc,  0><<<dim3(8, 16, Bb*4), 256>>>(x, base_w, base_b);
    gate1x1_k<<<(Bb*HW + 255)/256, 256>>>(gw2, gb2);
    deform_gemm_k<<<Bb*(HW/128), 256>>>(def_b, out);
}

// round 7
// speedup vs baseline: 1.1313x; 1.1313x over previous
#include <cuda_runtime.h>
#include <math.h>

#define PI_F 3.14159265358979323846f
#define Bb   2
#define Cc   128
#define Hh   128
#define Ww   256
#define HW   32768
#define AUXC 133
#define KWF  129

__device__ float2 g_R[Bb*KWF*Cc*Hh];
__device__ float  g_part[Bb*KWF*64*128];
__device__ float  g_feh[Bb*Hh*KWF];
__device__ float  g_fe[Bb*HW];
__device__ float  g_off[Bb*18*HW];
__device__ float  g_gbuf[Bb*66*HW];
__device__ float  g_gate[Bb*HW];
__device__ float  g_ybase[Bb*Cc*HW];
__device__ float  g_xT[Bb*HW*Cc];
__device__ float  g_wP[9*Cc*Cc];
__device__ float  g_wF[84*AUXC*9];     // fused offset(0-17)+gate(18-83) weights
__device__ float  g_bF[96];

// ---------------- FFT over W (256-pt real, keep bins 0..128) -------------
__global__ void fft_rows_k(const float* __restrict__ x) {
    __shared__ float2 sm[256];
    __shared__ float2 tw[128];
    int bid = blockIdx.x;
    int m = bid & (Hh-1), c = (bid >> 7) & (Cc-1), b = bid >> 14;
    int tid = threadIdx.x;
    float ang = -2.0f*PI_F*(float)tid/256.0f;
    tw[tid] = make_float2(cosf(ang), sinf(ang));
    const float* row = x + ((size_t)(b*Cc + c)*Hh + m)*Ww;
    for (int i = tid; i < 256; i += 128)
        sm[__brev(i) >> 24] = make_float2(row[i], 0.0f);
    __syncthreads();
#pragma unroll
    for (int s = 1; s <= 8; s++) {
        int half = 1 << (s-1);
        int pos = tid & (half-1);
        int i0 = ((tid >> (s-1)) << s) | pos, i1 = i0 + half;
        float2 w = tw[pos << (8-s)];
        float2 a = sm[i0], bv = sm[i1];
        float2 t = make_float2(bv.x*w.x - bv.y*w.y, bv.x*w.y + bv.y*w.x);
        sm[i0] = make_float2(a.x + t.x, a.y + t.y);
        sm[i1] = make_float2(a.x - t.x, a.y - t.y);
        __syncthreads();
    }
    g_R[((size_t)(b*KWF + tid)*Cc + c)*Hh + m] = sm[tid];
    if (tid == 0)
        g_R[((size_t)(b*KWF + 128)*Cc + c)*Hh + m] = sm[128];
}

// ---------------- FFT over H: one block per (b,kw,channel-pair) ----------
__global__ void fft_cols_k(void) {
    __shared__ float2 sm[2][128];
    __shared__ float2 tw[64];
    __shared__ float  mg[128];
    int bid = blockIdx.x;
    int cp = bid & 63, kw = (bid >> 6) % KWF, b = bid / (64*KWF);
    int tid = threadIdx.x, lane = tid & 63, f = tid >> 6;
    int c = cp*2 + f;
    if (tid < 64) {
        float ang = -2.0f*PI_F*(float)tid/128.0f;
        tw[tid] = make_float2(cosf(ang), sinf(ang));
    }
    const float2* base = g_R + (size_t)(b*KWF + kw)*Cc*Hh + c*Hh;
#pragma unroll
    for (int i = lane; i < 128; i += 64)
        sm[f][__brev(i) >> 25] = base[i];
    __syncthreads();
#pragma unroll
    for (int s = 1; s <= 7; s++) {
        int half = 1 << (s-1);
        int pos = lane & (half-1);
        int i0 = ((lane >> (s-1)) << s) | pos, i1 = i0 + half;
        float2 w = tw[pos << (7-s)];
        float2 a = sm[f][i0], bv = sm[f][i1];
        float2 t = make_float2(bv.x*w.x - bv.y*w.y, bv.x*w.y + bv.y*w.x);
        sm[f][i0] = make_float2(a.x + t.x, a.y + t.y);
        sm[f][i1] = make_float2(a.x - t.x, a.y - t.y);
        __syncthreads();
    }
    if (f == 0)
        for (int i = lane; i < 128; i += 64) {
            float2 X = sm[0][i];
            mg[i] = sqrtf(X.x*X.x + X.y*X.y);
        }
    __syncthreads();
    if (f == 1)
        for (int i = lane; i < 128; i += 64) {
            float2 X = sm[1][i];
            g_part[(size_t)bid*128 + i] = mg[i] + sqrtf(X.x*X.x + X.y*X.y);
        }
}

__global__ void reduce_feh_k(void) {
    int bid = blockIdx.x;           // b*KWF + kw
    int kw = bid % KWF, b = bid / KWF;
    int kh = threadIdx.x;
    float s = 0.0f;
    const float* p = g_part + (size_t)bid*64*128 + kh;
#pragma unroll 8
    for (int cp = 0; cp < 64; cp++) s += p[cp*128];
    g_feh[(size_t)(b*Hh + kh)*KWF + kw] = s * (1.0f/(128.0f*sqrtf((float)HW)));
}

__global__ void resize_fe_k(void) {
    int idx = blockIdx.x*blockDim.x + threadIdx.x;
    if (idx >= Bb*HW) return;
    int w = idx & (Ww-1), h = (idx >> 8) & (Hh-1), b = idx >> 15;
    float px = ((float)w + 0.5f)*(129.0f/256.0f) - 0.5f;
    float x0f = floorf(px);
    float f = px - x0f;
    int x0 = min(max((int)x0f, 0), 128), x1 = min(max((int)x0f + 1, 0), 128);
    const float* r = g_feh + (size_t)(b*Hh + h)*KWF;
    g_fe[idx] = r[x0]*(1.0f-f) + r[x1]*f;
}

// ---------------- NCHW -> NHWC transpose -------------------------------
__global__ void transpose_k(const float* __restrict__ x) {
    __shared__ float t[32][33];
    int b = blockIdx.z, p0 = blockIdx.x*32, c0 = blockIdx.y*32;
    int tx = threadIdx.x, ty = threadIdx.y;
#pragma unroll
    for (int j = 0; j < 4; j++)
        t[ty + j*8][tx] = x[(size_t)(b*Cc + c0 + ty + j*8)*HW + p0 + tx];
    __syncthreads();
#pragma unroll
    for (int j = 0; j < 4; j++)
        g_xT[(size_t)(b*HW + p0 + ty + j*8)*Cc + c0 + tx] = t[tx][ty + j*8];
}

__global__ void permw_k(const float* __restrict__ dw) {
    int idx = blockIdx.x*blockDim.x + threadIdx.x;
    if (idx >= 9*Cc*Cc) return;
    int co = idx & 127, ci = (idx >> 7) & 127, kk = idx >> 14;
    g_wP[idx] = dw[(size_t)(co*Cc + ci)*9 + kk];
}

// ---------------- fused aux weights: [84][133][9] + bias ----------------
__global__ void wfuse_k(const float* __restrict__ ow, const float* __restrict__ ob,
                        const float* __restrict__ gw, const float* __restrict__ gb) {
    int idx = blockIdx.x*blockDim.x + threadIdx.x;
    if (idx < 84*AUXC*9) {
        int co = idx / (AUXC*9), r = idx % (AUXC*9);
        g_wF[idx] = (co < 18) ? ow[(size_t)co*AUXC*9 + r] : gw[(size_t)(co-18)*AUXC*9 + r];
    }
    if (idx < 96) g_bF[idx] = (idx < 18) ? ob[idx] : (idx < 84 ? gb[idx-18] : 0.0f);
}

// ---------------- direct 3x3 conv, pad 1 --------------------------------
// MODE 0: fused aux conv (virtual input: x ++ coords ++ fe), weights from
//         g_wF/g_bF device symbols, CIN=133, COUT=84
// MODE 1: base conv, in = x, weights from args, out = g_ybase, COUT=128
template<int MODE, int CIN, int COUT>
__global__ void __launch_bounds__(256) conv3x3_t(
        const float* __restrict__ xin, const float* __restrict__ wgt_a,
        const float* __restrict__ bias_a) {
    const float* wgt  = (MODE == 0) ? g_wF : wgt_a;
    const float* bias = (MODE == 0) ? g_bF : bias_a;
    __shared__ float tile[6][34];
    __shared__ float ws[32][9];
    int tid = threadIdx.x;
    int xt = tid & 31, ct = tid >> 5;
    int x0 = blockIdx.x*32, y0 = blockIdx.y*4;
    const int nCoBlk = (COUT + 31) >> 5;
    int b = blockIdx.z / nCoBlk;
    int coB = (blockIdx.z % nCoBlk)*32;
    float acc[4][4];
#pragma unroll
    for (int j = 0; j < 4; j++)
#pragma unroll
        for (int y = 0; y < 4; y++) acc[j][y] = 0.0f;

    for (int ci = 0; ci < CIN; ci++) {
        if (tid < 204) {
            int r = tid/34, cc = tid%34;
            int gy = y0 + r - 1, gx = x0 + cc - 1;
            float v = 0.0f;
            if (gy >= 0 && gy < Hh && gx >= 0 && gx < Ww) {
                if (MODE == 1 || ci < Cc)
                    v = xin[((size_t)(b*Cc + ci)*Hh + gy)*Ww + gx];   // x has Cc channels
                else if (ci == 128) v = sinf(-PI_F + (2.0f*PI_F/255.0f)*(float)gx);
                else if (ci == 129) v = cosf(-PI_F + (2.0f*PI_F/255.0f)*(float)gx);
                else if (ci == 130) v = sinf(-0.5f*PI_F + (PI_F/127.0f)*(float)gy);
                else if (ci == 131) v = cosf(-0.5f*PI_F + (PI_F/127.0f)*(float)gy);
                else v = g_fe[(size_t)b*HW + gy*Ww + gx];
            }
            tile[r][cc] = v;
        }
        for (int i = tid; i < 288; i += 256) {
            int co = i/9, tap = i%9;
            int gco = coB + co;
            ws[co][tap] = (gco < COUT) ? wgt[(size_t)(gco*CIN + ci)*9 + tap] : 0.0f;
        }
        __syncthreads();
        float v[6][3];
#pragma unroll
        for (int r = 0; r < 6; r++)
#pragma unroll
            for (int k = 0; k < 3; k++) v[r][k] = tile[r][xt + k];
#pragma unroll
        for (int j = 0; j < 4; j++) {
            float wr[9];
#pragma unroll
            for (int t = 0; t < 9; t++) wr[t] = ws[ct*4 + j][t];
#pragma unroll
            for (int y = 0; y < 4; y++) {
                float s = acc[j][y];
                s = fmaf(v[y  ][0], wr[0], s); s = fmaf(v[y  ][1], wr[1], s); s = fmaf(v[y  ][2], wr[2], s);
                s = fmaf(v[y+1][0], wr[3], s); s = fmaf(v[y+1][1], wr[4], s); s = fmaf(v[y+1][2], wr[5], s);
                s = fmaf(v[y+2][0], wr[6], s); s = fmaf(v[y+2][1], wr[7], s); s = fmaf(v[y+2][2], wr[8], s);
                acc[j][y] = s;
            }
        }
        __syncthreads();
    }
#pragma unroll
    for (int j = 0; j < 4; j++) {
        int co = coB + ct*4 + j;
        if (co < COUT) {
            float bs = bias[co];
            float* op;
            bool relu = false;
            if (MODE == 1) {
                op = g_ybase + (size_t)(b*Cc + co)*HW;
            } else if (co < 18) {
                op = g_off + (size_t)(b*18 + co)*HW;
            } else {
                op = g_gbuf + (size_t)(b*66 + co - 18)*HW;
                relu = true;
            }
#pragma unroll
            for (int y = 0; y < 4; y++) {
                float o = acc[j][y] + bs;
                if (relu) o = fmaxf(o, 0.0f);
                op[(size_t)(y0 + y)*Ww + x0 + xt] = o;
            }
        }
    }
}

// ---------------- 1x1 gate conv + sigmoid -------------------------------
__global__ void gate1x1_k(const float* __restrict__ w2, const float* __restrict__ b2) {
    int idx = blockIdx.x*blockDim.x + threadIdx.x;
    if (idx >= Bb*HW) return;
    int b = idx >> 15, p = idx & (HW-1);
    float s = b2[0];
#pragma unroll 6
    for (int c = 0; c < 66; c++)
        s = fmaf(g_gbuf[(size_t)(b*66 + c)*HW + p], w2[c], s);
    g_gate[idx] = 1.0f / (1.0f + expf(-s));
}

// ---------------- fused deform-sample + 1x1 GEMM + blend ----------------
__global__ void __launch_bounds__(256) deform_gemm_k(
        const float* __restrict__ defb, float* __restrict__ out) {
    __shared__ float Ssm[32][128];
    __shared__ float Wsm[32][128];
    __shared__ int   mX0[128], mY0[128];
    __shared__ float mFx[128], mFy[128];
    int tid = threadIdx.x;
    int blk = blockIdx.x;
    int b = blk >> 8, pix0 = (blk & 255)*128;
    int coIdx = (tid & 15)*8, pxIdx = (tid >> 4)*8;
    float acc[8][8];
#pragma unroll
    for (int i = 0; i < 8; i++)
#pragma unroll
        for (int j = 0; j < 8; j++) acc[i][j] = 0.0f;
    int p = tid >> 1, sub = tid & 1;

#pragma unroll 1
    for (int kk = 0; kk < 9; kk++) {
        __syncthreads();
        if (tid < 128) {
            int pp = pix0 + tid;
            int hh = pp >> 8, ww = pp & (Ww-1);
            float fpx = (float)ww + g_off[(size_t)(b*18 + 2*kk    )*HW + pp];
            float fpy = (float)hh + g_off[(size_t)(b*18 + 2*kk + 1)*HW + pp];
            float fx0 = floorf(fpx), fy0 = floorf(fpy);
            mX0[tid] = (int)fx0;  mY0[tid] = (int)fy0;
            mFx[tid] = fpx - fx0; mFy[tid] = fpy - fy0;
        }
        __syncthreads();
        int X0 = mX0[p], Y0 = mY0[p];
        float fx = mFx[p], fy = mFy[p];
        float w00 = (1.0f-fx)*(1.0f-fy), w10 = fx*(1.0f-fy);
        float w01 = (1.0f-fx)*fy,        w11 = fx*fy;
        if (X0   < 0 || X0   >= Ww) { w00 = 0.0f; w01 = 0.0f; }
        if (X0+1 < 0 || X0+1 >= Ww) { w10 = 0.0f; w11 = 0.0f; }
        if (Y0   < 0 || Y0   >= Hh) { w00 = 0.0f; w10 = 0.0f; }
        if (Y0+1 < 0 || Y0+1 >= Hh) { w01 = 0.0f; w11 = 0.0f; }
        int cx0 = min(max(X0, 0), Ww-1), cx1 = min(max(X0+1, 0), Ww-1);
        int cy0 = min(max(Y0, 0), Hh-1), cy1 = min(max(Y0+1, 0), Hh-1);
        const float4* p00 = (const float4*)(g_xT + ((size_t)(b*Hh + cy0)*Ww + cx0)*Cc);
        const float4* p10 = (const float4*)(g_xT + ((size_t)(b*Hh + cy0)*Ww + cx1)*Cc);
        const float4* p01 = (const float4*)(g_xT + ((size_t)(b*Hh + cy1)*Ww + cx0)*Cc);
        const float4* p11 = (const float4*)(g_xT + ((size_t)(b*Hh + cy1)*Ww + cx1)*Cc);

#pragma unroll 1
        for (int cc = 0; cc < 4; cc++) {
            __syncthreads();
            int cb = sub*16, cig = cc*32 + cb;
#pragma unroll
            for (int q = 0; q < 4; q++) {
                int f4 = (cig >> 2) + q;
                float4 a00 = p00[f4], a10 = p10[f4], a01 = p01[f4], a11 = p11[f4];
                float4 r;
                r.x = w00*a00.x + w10*a10.x + w01*a01.x + w11*a11.x;
                r.y = w00*a00.y + w10*a10.y + w01*a01.y + w11*a11.y;
                r.z = w00*a00.z + w10*a10.z + w01*a01.z + w11*a11.z;
                r.w = w00*a00.w + w10*a10.w + w01*a01.w + w11*a11.w;
                Ssm[cb + q*4 + 0][p] = r.x;
                Ssm[cb + q*4 + 1][p] = r.y;
                Ssm[cb + q*4 + 2][p] = r.z;
                Ssm[cb + q*4 + 3][p] = r.w;
            }
            int krow0 = kk*128 + cc*32;
            {
                const float4* wsrc = (const float4*)(g_wP + (size_t)krow0*Cc);
                float4* wdst = (float4*)&Wsm[0][0];
                for (int i = tid; i < 1024; i += 256) wdst[i] = wsrc[i];
            }
            __syncthreads();
#pragma unroll 8
            for (int kq = 0; kq < 32; kq++) {
                float4 a0 = *(const float4*)&Wsm[kq][coIdx];
                float4 a1 = *(const float4*)&Wsm[kq][coIdx+4];
                float4 b0 = *(const float4*)&Ssm[kq][pxIdx];
                float4 b1 = *(const float4*)&Ssm[kq][pxIdx+4];
                float av[8] = {a0.x,a0.y,a0.z,a0.w,a1.x,a1.y,a1.z,a1.w};
                float bv[8] = {b0.x,b0.y,b0.z,b0.w,b1.x,b1.y,b1.z,b1.w};
#pragma unroll
                for (int i = 0; i < 8; i++)
#pragma unroll
                    for (int j = 0; j < 8; j++)
                        acc[i][j] = fmaf(av[i], bv[j], acc[i][j]);
            }
        }
    }
    int pixg = pix0 + pxIdx;
    float gt[8];
#pragma unroll
    for (int j = 0; j < 8; j++) gt[j] = g_gate[(size_t)b*HW + pixg + j];
#pragma unroll
    for (int i = 0; i < 8; i++) {
        int co = coIdx + i;
        float bs = defb[co];
        const float* yb = g_ybase + (size_t)(b*Cc + co)*HW + pixg;
        float* op = out + (size_t)(b*Cc + co)*HW + pixg;
#pragma unroll
        for (int j = 0; j < 8; j++) {
            float yd = acc[i][j] + bs;
            op[j] = (1.0f - gt[j])*yb[j] + gt[j]*yd;
        }
    }
}

// ---------------- host launcher -----------------------------------------
extern "C" void kernel_launch(void* const* d_in, const int* in_sizes, int n_in,
                              void* d_out, int out_size) {
    const float* x      = (const float*)d_in[0];
    const float* off_w  = (const float*)d_in[1];
    const float* off_b  = (const float*)d_in[2];
    const float* gw1    = (const float*)d_in[3];
    const float* gb1    = (const float*)d_in[4];
    const float* gw2    = (const float*)d_in[5];
    const float* gb2    = (const float*)d_in[6];
    const float* base_w = (const float*)d_in[7];
    const float* base_b = (const float*)d_in[8];
    const float* def_w  = (const float*)d_in[9];
    const float* def_b  = (const float*)d_in[10];
    float* out = (float*)d_out;

    fft_rows_k<<<Bb*Cc*Hh, 128>>>(x);
    fft_cols_k<<<Bb*KWF*64, 128>>>();
    reduce_feh_k<<<Bb*KWF, 128>>>();
    transpose_k<<<dim3(HW/32, Cc/32, Bb), dim3(32, 8)>>>(x);
    permw_k<<<(9*Cc*Cc + 255)/256, 256>>>(def_w);
    conv3x3_t<1, Cc, Cc><<<dim3(8, 32, Bb*4), 256>>>(x, base_w, base_b);  // slot 6 (profiled)
    resize_fe_k<<<(Bb*HW + 255)/256, 256>>>();
    wfuse_k<<<(84*AUXC*9 + 255)/256, 256>>>(off_w, off_b, gw1, gb1);
    conv3x3_t<0, AUXC, 84><<<dim3(8, 32, Bb*3), 256>>>(x, nullptr, nullptr);
    gate1x1_k<<<(Bb*HW + 255)/256, 256>>>(gw2, gb2);
    deform_gemm_k<<<Bb*(HW/128), 256>>>(def_b, out);
}

// round 9
// speedup vs baseline: 1.4022x; 1.2394x over previous
#include <cuda_runtime.h>
#include <cuda_bf16.h>
#include <math.h>

#define PI_F 3.14159265358979323846f
#define Bb   2
#define Cc   128
#define Hh   128
#define Ww   256
#define HW   32768
#define AUXC 133
#define KWF  129
#define ASTR 88            // smem row stride (bf16 elems): 176B, 16B-aligned, LDSM conflict-free

__device__ float2 g_R[Bb*KWF*Cc*Hh];
__device__ float  g_part[Bb*KWF*64*128];
__device__ float  g_feh[Bb*Hh*KWF];
__device__ float  g_fe[Bb*HW];
__device__ float  g_off[Bb*18*HW];
__device__ float  g_gbuf[Bb*66*HW];
__device__ float  g_gate[Bb*HW];
__device__ float  g_ybase[Bb*Cc*HW];
__device__ float  g_xT[Bb*HW*Cc];
__device__ float  g_wP[9*Cc*Cc];
__device__ float  g_wF[84*AUXC*9];
__device__ float  g_bF[96];
__device__ __align__(16) __nv_bfloat16 g_xbh[(size_t)Bb*HW*Cc];
__device__ __align__(16) __nv_bfloat16 g_xbl[(size_t)Bb*HW*Cc];
__device__ __align__(16) __nv_bfloat16 g_WBh[18*8192];   // [chunk][co][64]
__device__ __align__(16) __nv_bfloat16 g_WBl[18*8192];

__device__ __forceinline__ unsigned smem_u32(const void* p){
    unsigned r;
    asm("{.reg .u64 t; cvta.to.shared.u64 t, %1; cvt.u32.u64 %0, t;}" : "=r"(r) : "l"(p));
    return r;
}
__device__ __forceinline__ void ldsm4(unsigned* r, unsigned a){
    asm volatile("ldmatrix.sync.aligned.m8n8.x4.shared.b16 {%0,%1,%2,%3}, [%4];"
        : "=r"(r[0]),"=r"(r[1]),"=r"(r[2]),"=r"(r[3]) : "r"(a));
}
__device__ __forceinline__ void mma16816(float* d, const unsigned* a, unsigned b0, unsigned b1){
    asm volatile("mma.sync.aligned.m16n8k16.row.col.f32.bf16.bf16.f32 "
        "{%0,%1,%2,%3}, {%4,%5,%6,%7}, {%8,%9}, {%0,%1,%2,%3};"
        : "+f"(d[0]),"+f"(d[1]),"+f"(d[2]),"+f"(d[3])
        : "r"(a[0]),"r"(a[1]),"r"(a[2]),"r"(a[3]), "r"(b0),"r"(b1));
}

// ---------------- FFT over W ---------------------------------------------
__global__ void fft_rows_k(const float* __restrict__ x) {
    __shared__ float2 sm[256];
    __shared__ float2 tw[128];
    int bid = blockIdx.x;
    int m = bid & (Hh-1), c = (bid >> 7) & (Cc-1), b = bid >> 14;
    int tid = threadIdx.x;
    float ang = -2.0f*PI_F*(float)tid/256.0f;
    tw[tid] = make_float2(cosf(ang), sinf(ang));
    const float* row = x + ((size_t)(b*Cc + c)*Hh + m)*Ww;
    for (int i = tid; i < 256; i += 128)
        sm[__brev(i) >> 24] = make_float2(row[i], 0.0f);
    __syncthreads();
#pragma unroll
    for (int s = 1; s <= 8; s++) {
        int half = 1 << (s-1);
        int pos = tid & (half-1);
        int i0 = ((tid >> (s-1)) << s) | pos, i1 = i0 + half;
        float2 w = tw[pos << (8-s)];
        float2 a = sm[i0], bv = sm[i1];
        float2 t = make_float2(bv.x*w.x - bv.y*w.y, bv.x*w.y + bv.y*w.x);
        sm[i0] = make_float2(a.x + t.x, a.y + t.y);
        sm[i1] = make_float2(a.x - t.x, a.y - t.y);
        __syncthreads();
    }
    g_R[((size_t)(b*KWF + tid)*Cc + c)*Hh + m] = sm[tid];
    if (tid == 0)
        g_R[((size_t)(b*KWF + 128)*Cc + c)*Hh + m] = sm[128];
}

// ---------------- FFT over H ---------------------------------------------
__global__ void fft_cols_k(void) {
    __shared__ float2 sm[2][128];
    __shared__ float2 tw[64];
    __shared__ float  mg[128];
    int bid = blockIdx.x;
    int cp = bid & 63, kw = (bid >> 6) % KWF, b = bid / (64*KWF);
    int tid = threadIdx.x, lane = tid & 63, f = tid >> 6;
    int c = cp*2 + f;
    if (tid < 64) {
        float ang = -2.0f*PI_F*(float)tid/128.0f;
        tw[tid] = make_float2(cosf(ang), sinf(ang));
    }
    const float2* base = g_R + (size_t)(b*KWF + kw)*Cc*Hh + c*Hh;
#pragma unroll
    for (int i = lane; i < 128; i += 64)
        sm[f][__brev(i) >> 25] = base[i];
    __syncthreads();
#pragma unroll
    for (int s = 1; s <= 7; s++) {
        int half = 1 << (s-1);
        int pos = lane & (half-1);
        int i0 = ((lane >> (s-1)) << s) | pos, i1 = i0 + half;
        float2 w = tw[pos << (7-s)];
        float2 a = sm[f][i0], bv = sm[f][i1];
        float2 t = make_float2(bv.x*w.x - bv.y*w.y, bv.x*w.y + bv.y*w.x);
        sm[f][i0] = make_float2(a.x + t.x, a.y + t.y);
        sm[f][i1] = make_float2(a.x - t.x, a.y - t.y);
        __syncthreads();
    }
    if (f == 0)
        for (int i = lane; i < 128; i += 64) {
            float2 X = sm[0][i];
            mg[i] = sqrtf(X.x*X.x + X.y*X.y);
        }
    __syncthreads();
    if (f == 1)
        for (int i = lane; i < 128; i += 64) {
            float2 X = sm[1][i];
            g_part[(size_t)bid*128 + i] = mg[i] + sqrtf(X.x*X.x + X.y*X.y);
        }
}

__global__ void reduce_feh_k(void) {
    int bid = blockIdx.x;
    int kw = bid % KWF, b = bid / KWF;
    int kh = threadIdx.x;
    float s = 0.0f;
    const float* p = g_part + (size_t)bid*64*128 + kh;
#pragma unroll 8
    for (int cp = 0; cp < 64; cp++) s += p[cp*128];
    g_feh[(size_t)(b*Hh + kh)*KWF + kw] = s * (1.0f/(128.0f*sqrtf((float)HW)));
}

__global__ void resize_fe_k(void) {
    int idx = blockIdx.x*blockDim.x + threadIdx.x;
    if (idx >= Bb*HW) return;
    int w = idx & (Ww-1), h = (idx >> 8) & (Hh-1), b = idx >> 15;
    float px = ((float)w + 0.5f)*(129.0f/256.0f) - 0.5f;
    float x0f = floorf(px);
    float f = px - x0f;
    int x0 = min(max((int)x0f, 0), 128), x1 = min(max((int)x0f + 1, 0), 128);
    const float* r = g_feh + (size_t)(b*Hh + h)*KWF;
    g_fe[idx] = r[x0]*(1.0f-f) + r[x1]*f;
}

// ---------------- transpose + bf16 hi/lo split ---------------------------
__global__ void transpose_k(const float* __restrict__ x) {
    __shared__ float t[32][33];
    int b = blockIdx.z, p0 = blockIdx.x*32, c0 = blockIdx.y*32;
    int tx = threadIdx.x, ty = threadIdx.y;
#pragma unroll
    for (int j = 0; j < 4; j++)
        t[ty + j*8][tx] = x[(size_t)(b*Cc + c0 + ty + j*8)*HW + p0 + tx];
    __syncthreads();
#pragma unroll
    for (int j = 0; j < 4; j++) {
        float v = t[tx][ty + j*8];
        size_t o = (size_t)(b*HW + p0 + ty + j*8)*Cc + c0 + tx;
        g_xT[o] = v;
        __nv_bfloat16 hb = __float2bfloat16(v);
        g_xbh[o] = hb;
        g_xbl[o] = __float2bfloat16(v - __bfloat162float(hb));
    }
}

__global__ void permw_k(const float* __restrict__ dw) {
    int idx = blockIdx.x*blockDim.x + threadIdx.x;
    if (idx >= 9*Cc*Cc) return;
    int co = idx & 127, ci = (idx >> 7) & 127, kk = idx >> 14;
    g_wP[idx] = dw[(size_t)(co*Cc + ci)*9 + kk];
}

// ---------------- base W -> [chunk][co][64] bf16 hi/lo -------------------
__global__ void wprep_k(const float* __restrict__ bw) {
    int idx = blockIdx.x*blockDim.x + threadIdx.x;
    if (idx >= 18*8192) return;
    int c = idx >> 13, r = idx & 8191;
    int co = r >> 6, k = r & 63;
    int kk = c >> 1, ci = (c & 1)*64 + k;
    float v = bw[(size_t)(co*Cc + ci)*9 + kk];
    __nv_bfloat16 hb = __float2bfloat16(v);
    g_WBh[idx] = hb;
    g_WBl[idx] = __float2bfloat16(v - __bfloat162float(hb));
}

// ---------------- mma.sync base conv: 128co x 128px per CTA --------------
__global__ void __launch_bounds__(256) conv_mma(const float* __restrict__ bias) {
    extern __shared__ __align__(16) unsigned char dsm[];
    __nv_bfloat16* Ah = (__nv_bfloat16*)dsm;                 // [128][ASTR]
    __nv_bfloat16* Al = Ah + 128*ASTR;
    __nv_bfloat16* Bh = Al + 128*ASTR;
    __nv_bfloat16* Bl = Bh + 128*ASTR;
    int tid = threadIdx.x;
    int wid = tid >> 5, lane = tid & 31;
    int mw = wid & 1, nw = wid >> 1;
    int co0 = mw*64, pxo = nw*32;
    int blk = blockIdx.x;
    int b = blk >> 8;
    int px0 = (blk & 255) * 128;
    int h = px0 >> 8, w0 = px0 & 255;
    int r15 = lane & 15, r16 = (lane >> 4)*8;

    float acc[4][4][4];
#pragma unroll
    for (int mf = 0; mf < 4; mf++)
#pragma unroll
        for (int nf = 0; nf < 4; nf++)
#pragma unroll
            for (int q = 0; q < 4; q++) acc[mf][nf][q] = 0.0f;

    for (int c = 0; c < 18; c++) {
        int kk = c >> 1;
        int dy = kk/3 - 1, dx = kk%3 - 1;
        int ci0 = (c & 1)*64;
        __syncthreads();
        // A fill: weights [co][64] -> [co][ASTR]
        for (int i = tid; i < 2048; i += 256) {
            int buf = i >> 10, idx = i & 1023;
            int row = idx >> 3, seg = idx & 7;
            const float4* src = (const float4*)((buf ? g_WBl : g_WBh) + (size_t)c*8192 + row*64) + seg;
            float4* dst = (float4*)((buf ? Al : Ah) + row*ASTR) + seg;
            *dst = *src;
        }
        // B fill: x rows with (dy,dx) shift, zero border
        int sh = h + dy;
        for (int i = tid; i < 2048; i += 256) {
            int buf = i >> 10, idx = i & 1023;
            int p = idx >> 3, seg = idx & 7;
            int sw = w0 + p + dx;
            float4 v = make_float4(0.f,0.f,0.f,0.f);
            if (sw >= 0 && sw < Ww && sh >= 0 && sh < Hh)
                v = *((const float4*)((buf ? g_xbl : g_xbh) +
                      ((size_t)(b*HW) + sh*Ww + sw)*Cc + ci0) + seg);
            *((float4*)((buf ? Bl : Bh) + p*ASTR) + seg) = v;
        }
        __syncthreads();
#pragma unroll
        for (int ks = 0; ks < 4; ks++) {
            unsigned bh[2][4], bl[2][4];
#pragma unroll
            for (int nh = 0; nh < 2; nh++) {
                unsigned ab = smem_u32(Bh + (pxo + nh*16 + r15)*ASTR + ks*16 + r16);
                ldsm4(bh[nh], ab);
                unsigned al2 = smem_u32(Bl + (pxo + nh*16 + r15)*ASTR + ks*16 + r16);
                ldsm4(bl[nh], al2);
            }
#pragma unroll
            for (int mf = 0; mf < 4; mf++) {
                unsigned ah[4], al[4];
                ldsm4(ah, smem_u32(Ah + (co0 + mf*16 + r15)*ASTR + ks*16 + r16));
                ldsm4(al, smem_u32(Al + (co0 + mf*16 + r15)*ASTR + ks*16 + r16));
#pragma unroll
                for (int nf = 0; nf < 4; nf++) {
                    int nh = nf >> 1, sel = nf & 1;
                    unsigned b0h = bh[nh][sel], b1h = bh[nh][sel+2];
                    unsigned b0l = bl[nh][sel], b1l = bl[nh][sel+2];
                    mma16816(acc[mf][nf], ah, b0h, b1h);
                    mma16816(acc[mf][nf], ah, b0l, b1l);
                    mma16816(acc[mf][nf], al, b0h, b1h);
                }
            }
        }
    }
    // epilogue
    int gid = lane >> 2, t4 = lane & 3;
#pragma unroll
    for (int mf = 0; mf < 4; mf++) {
#pragma unroll
        for (int nf = 0; nf < 4; nf++) {
            int co = co0 + mf*16 + gid;
            int px = px0 + pxo + nf*8 + t4*2;
            float* d = acc[mf][nf];
            float2 o0 = make_float2(d[0] + bias[co],     d[1] + bias[co]);
            float2 o1 = make_float2(d[2] + bias[co+8],   d[3] + bias[co+8]);
            *(float2*)(g_ybase + (size_t)(b*Cc + co  )*HW + px) = o0;
            *(float2*)(g_ybase + (size_t)(b*Cc + co+8)*HW + px) = o1;
        }
    }
}

// ---------------- fused aux weights --------------------------------------
__global__ void wfuse_k(const float* __restrict__ ow, const float* __restrict__ ob,
                        const float* __restrict__ gw, const float* __restrict__ gb) {
    int idx = blockIdx.x*blockDim.x + threadIdx.x;
    if (idx < 84*AUXC*9) {
        int co = idx / (AUXC*9), r = idx % (AUXC*9);
        g_wF[idx] = (co < 18) ? ow[(size_t)co*AUXC*9 + r] : gw[(size_t)(co-18)*AUXC*9 + r];
    }
    if (idx < 96) g_bF[idx] = (idx < 18) ? ob[idx] : (idx < 84 ? gb[idx-18] : 0.0f);
}

// ---------------- aux conv (offset 0-17, gate 18-83), scalar -------------
__global__ void __launch_bounds__(256) conv_aux_k(const float* __restrict__ xin) {
    __shared__ float tile[6][34];
    __shared__ float ws[32][9];
    int tid = threadIdx.x;
    int xt = tid & 31, ct = tid >> 5;
    int x0 = blockIdx.x*32, y0 = blockIdx.y*4;
    int b = blockIdx.z / 3;
    int coB = (blockIdx.z % 3)*32;
    float acc[4][4];
#pragma unroll
    for (int j = 0; j < 4; j++)
#pragma unroll
        for (int y = 0; y < 4; y++) acc[j][y] = 0.0f;

    for (int ci = 0; ci < AUXC; ci++) {
        if (tid < 204) {
            int r = tid/34, cc = tid%34;
            int gy = y0 + r - 1, gx = x0 + cc - 1;
            float v = 0.0f;
            if (gy >= 0 && gy < Hh && gx >= 0 && gx < Ww) {
                if (ci < Cc)        v = xin[((size_t)(b*Cc + ci)*Hh + gy)*Ww + gx];
                else if (ci == 128) v = sinf(-PI_F + (2.0f*PI_F/255.0f)*(float)gx);
                else if (ci == 129) v = cosf(-PI_F + (2.0f*PI_F/255.0f)*(float)gx);
                else if (ci == 130) v = sinf(-0.5f*PI_F + (PI_F/127.0f)*(float)gy);
                else if (ci == 131) v = cosf(-0.5f*PI_F + (PI_F/127.0f)*(float)gy);
                else                v = g_fe[(size_t)b*HW + gy*Ww + gx];
            }
            tile[r][cc] = v;
        }
        for (int i = tid; i < 288; i += 256) {
            int co = i/9, tap = i%9;
            int gco = coB + co;
            ws[co][tap] = (gco < 84) ? g_wF[(size_t)(gco*AUXC + ci)*9 + tap] : 0.0f;
        }
        __syncthreads();
        float v[6][3];
#pragma unroll
        for (int r = 0; r < 6; r++)
#pragma unroll
            for (int k = 0; k < 3; k++) v[r][k] = tile[r][xt + k];
#pragma unroll
        for (int j = 0; j < 4; j++) {
            float wr[9];
#pragma unroll
            for (int t = 0; t < 9; t++) wr[t] = ws[ct*4 + j][t];
#pragma unroll
            for (int y = 0; y < 4; y++) {
                float s = acc[j][y];
                s = fmaf(v[y  ][0], wr[0], s); s = fmaf(v[y  ][1], wr[1], s); s = fmaf(v[y  ][2], wr[2], s);
                s = fmaf(v[y+1][0], wr[3], s); s = fmaf(v[y+1][1], wr[4], s); s = fmaf(v[y+1][2], wr[5], s);
                s = fmaf(v[y+2][0], wr[6], s); s = fmaf(v[y+2][1], wr[7], s); s = fmaf(v[y+2][2], wr[8], s);
                acc[j][y] = s;
            }
        }
        __syncthreads();
    }
#pragma unroll
    for (int j = 0; j < 4; j++) {
        int co = coB + ct*4 + j;
        if (co < 84) {
            float bs = g_bF[co];
            float* op;
            bool relu = false;
            if (co < 18) op = g_off + (size_t)(b*18 + co)*HW;
            else { op = g_gbuf + (size_t)(b*66 + co - 18)*HW; relu = true; }
#pragma unroll
            for (int y = 0; y < 4; y++) {
                float o = acc[j][y] + bs;
                if (relu) o = fmaxf(o, 0.0f);
                op[(size_t)(y0 + y)*Ww + x0 + xt] = o;
            }
        }
    }
}

__global__ void gate1x1_k(const float* __restrict__ w2, const float* __restrict__ b2) {
    int idx = blockIdx.x*blockDim.x + threadIdx.x;
    if (idx >= Bb*HW) return;
    int b = idx >> 15, p = idx & (HW-1);
    float s = b2[0];
#pragma unroll 6
    for (int c = 0; c < 66; c++)
        s = fmaf(g_gbuf[(size_t)(b*66 + c)*HW + p], w2[c], s);
    g_gate[idx] = 1.0f / (1.0f + expf(-s));
}

// ---------------- fused deform-sample + 1x1 GEMM + blend -----------------
__global__ void __launch_bounds__(256) deform_gemm_k(
        const float* __restrict__ defb, float* __restrict__ out) {
    __shared__ float Ssm[32][128];
    __shared__ float Wsm[32][128];
    __shared__ int   mX0[128], mY0[128];
    __shared__ float mFx[128], mFy[128];
    int tid = threadIdx.x;
    int blk = blockIdx.x;
    int b = blk >> 8, pix0 = (blk & 255)*128;
    int coIdx = (tid & 15)*8, pxIdx = (tid >> 4)*8;
    float acc[8][8];
#pragma unroll
    for (int i = 0; i < 8; i++)
#pragma unroll
        for (int j = 0; j < 8; j++) acc[i][j] = 0.0f;
    int p = tid >> 1, sub = tid & 1;

#pragma unroll 1
    for (int kk = 0; kk < 9; kk++) {
        __syncthreads();
        if (tid < 128) {
            int pp = pix0 + tid;
            int hh = pp >> 8, ww = pp & (Ww-1);
            float fpx = (float)ww + g_off[(size_t)(b*18 + 2*kk    )*HW + pp];
            float fpy = (float)hh + g_off[(size_t)(b*18 + 2*kk + 1)*HW + pp];
            float fx0 = floorf(fpx), fy0 = floorf(fpy);
            mX0[tid] = (int)fx0;  mY0[tid] = (int)fy0;
            mFx[tid] = fpx - fx0; mFy[tid] = fpy - fy0;
        }
        __syncthreads();
        int X0 = mX0[p], Y0 = mY0[p];
        float fx = mFx[p], fy = mFy[p];
        float w00 = (1.0f-fx)*(1.0f-fy), w10 = fx*(1.0f-fy);
        float w01 = (1.0f-fx)*fy,        w11 = fx*fy;
        if (X0   < 0 || X0   >= Ww) { w00 = 0.0f; w01 = 0.0f; }
        if (X0+1 < 0 || X0+1 >= Ww) { w10 = 0.0f; w11 = 0.0f; }
        if (Y0   < 0 || Y0   >= Hh) { w00 = 0.0f; w10 = 0.0f; }
        if (Y0+1 < 0 || Y0+1 >= Hh) { w01 = 0.0f; w11 = 0.0f; }
        int cx0 = min(max(X0, 0), Ww-1), cx1 = min(max(X0+1, 0), Ww-1);
        int cy0 = min(max(Y0, 0), Hh-1), cy1 = min(max(Y0+1, 0), Hh-1);
        const float4* p00 = (const float4*)(g_xT + ((size_t)(b*Hh + cy0)*Ww + cx0)*Cc);
        const float4* p10 = (const float4*)(g_xT + ((size_t)(b*Hh + cy0)*Ww + cx1)*Cc);
        const float4* p01 = (const float4*)(g_xT + ((size_t)(b*Hh + cy1)*Ww + cx0)*Cc);
        const float4* p11 = (const float4*)(g_xT + ((size_t)(b*Hh + cy1)*Ww + cx1)*Cc);

#pragma unroll 1
        for (int cc = 0; cc < 4; cc++) {
            __syncthreads();
            int cb = sub*16, cig = cc*32 + cb;
#pragma unroll
            for (int q = 0; q < 4; q++) {
                int f4 = (cig >> 2) + q;
                float4 a00 = p00[f4], a10 = p10[f4], a01 = p01[f4], a11 = p11[f4];
                float4 r;
                r.x = w00*a00.x + w10*a10.x + w01*a01.x + w11*a11.x;
                r.y = w00*a00.y + w10*a10.y + w01*a01.y + w11*a11.y;
                r.z = w00*a00.z + w10*a10.z + w01*a01.z + w11*a11.z;
                r.w = w00*a00.w + w10*a10.w + w01*a01.w + w11*a11.w;
                Ssm[cb + q*4 + 0][p] = r.x;
                Ssm[cb + q*4 + 1][p] = r.y;
                Ssm[cb + q*4 + 2][p] = r.z;
                Ssm[cb + q*4 + 3][p] = r.w;
            }
            int krow0 = kk*128 + cc*32;
            {
                const float4* wsrc = (const float4*)(g_wP + (size_t)krow0*Cc);
                float4* wdst = (float4*)&Wsm[0][0];
                for (int i = tid; i < 1024; i += 256) wdst[i] = wsrc[i];
            }
            __syncthreads();
#pragma unroll 8
            for (int kq = 0; kq < 32; kq++) {
                float4 a0 = *(const float4*)&Wsm[kq][coIdx];
                float4 a1 = *(const float4*)&Wsm[kq][coIdx+4];
                float4 b0 = *(const float4*)&Ssm[kq][pxIdx];
                float4 b1 = *(const float4*)&Ssm[kq][pxIdx+4];
                float av[8] = {a0.x,a0.y,a0.z,a0.w,a1.x,a1.y,a1.z,a1.w};
                float bv[8] = {b0.x,b0.y,b0.z,b0.w,b1.x,b1.y,b1.z,b1.w};
#pragma unroll
                for (int i = 0; i < 8; i++)
#pragma unroll
                    for (int j = 0; j < 8; j++)
                        acc[i][j] = fmaf(av[i], bv[j], acc[i][j]);
            }
        }
    }
    int pixg = pix0 + pxIdx;
    float gt[8];
#pragma unroll
    for (int j = 0; j < 8; j++) gt[j] = g_gate[(size_t)b*HW + pixg + j];
#pragma unroll
    for (int i = 0; i < 8; i++) {
        int co = coIdx + i;
        float bs = defb[co];
        const float* yb = g_ybase + (size_t)(b*Cc + co)*HW + pixg;
        float* op = out + (size_t)(b*Cc + co)*HW + pixg;
#pragma unroll
        for (int j = 0; j < 8; j++) {
            float yd = acc[i][j] + bs;
            op[j] = (1.0f - gt[j])*yb[j] + gt[j]*yd;
        }
    }
}

// ---------------- host launcher ------------------------------------------
extern "C" void kernel_launch(void* const* d_in, const int* in_sizes, int n_in,
                              void* d_out, int out_size) {
    const float* x      = (const float*)d_in[0];
    const float* off_w  = (const float*)d_in[1];
    const float* off_b  = (const float*)d_in[2];
    const float* gw1    = (const float*)d_in[3];
    const float* gb1    = (const float*)d_in[4];
    const float* gw2    = (const float*)d_in[5];
    const float* gb2    = (const float*)d_in[6];
    const float* base_w = (const float*)d_in[7];
    const float* base_b = (const float*)d_in[8];
    const float* def_w  = (const float*)d_in[9];
    const float* def_b  = (const float*)d_in[10];
    float* out = (float*)d_out;

    const int CMMA_SMEM = 4*128*ASTR*2;     // 90112 bytes
    cudaFuncSetAttribute(conv_mma, cudaFuncAttributeMaxDynamicSharedMemorySize, CMMA_SMEM);

    fft_rows_k<<<Bb*Cc*Hh, 128>>>(x);
    fft_cols_k<<<Bb*KWF*64, 128>>>();
    reduce_feh_k<<<Bb*KWF, 128>>>();
    transpose_k<<<dim3(HW/32, Cc/32, Bb), dim3(32, 8)>>>(x);
    permw_k<<<(9*Cc*Cc + 255)/256, 256>>>(def_w);
    wprep_k<<<(18*8192 + 255)/256, 256>>>(base_w);
    conv_mma<<<Bb*256, 256, CMMA_SMEM>>>(base_b);
    resize_fe_k<<<(Bb*HW + 255)/256, 256>>>();
    wfuse_k<<<(84*AUXC*9 + 255)/256, 256>>>(off_w, off_b, gw1, gb1);
    conv_aux_k<<<dim3(8, 32, Bb*3), 256>>>(x);
    gate1x1_k<<<(Bb*HW + 255)/256, 256>>>(gw2, gb2);
    deform_gemm_k<<<Bb*(HW/128), 256>>>(def_b, out);
}

// round 10
// speedup vs baseline: 1.7891x; 1.2759x over previous
#include <cuda_runtime.h>
#include <cuda_bf16.h>
#include <math.h>

#define PI_F 3.14159265358979323846f
#define Bb   2
#define Cc   128
#define Hh   128
#define Ww   256
#define HW   32768
#define AUXC 133
#define KWF  129
#define ASTR 88            // smem row stride (bf16 elems)

__device__ float2 g_R[Bb*KWF*Cc*Hh];
__device__ float  g_part[Bb*KWF*64*128];
__device__ float  g_feh[Bb*Hh*KWF];
__device__ float  g_fe[Bb*HW];
__device__ float  g_off[Bb*18*HW];
__device__ float  g_gbuf[Bb*66*HW];
__device__ float  g_gate[Bb*HW];
__device__ float  g_ybase[Bb*Cc*HW];
__device__ float  g_xT[Bb*HW*Cc];
__device__ float  g_wF[84*AUXC*9];
__device__ float  g_bF[96];
__device__ __align__(16) __nv_bfloat16 g_xbh[(size_t)Bb*HW*Cc];
__device__ __align__(16) __nv_bfloat16 g_xbl[(size_t)Bb*HW*Cc];
__device__ __align__(16) __nv_bfloat16 g_WBh[18*8192];   // base W [chunk][co][64]
__device__ __align__(16) __nv_bfloat16 g_WBl[18*8192];
__device__ __align__(16) __nv_bfloat16 g_WDh[18*8192];   // def  W [chunk][co][64]
__device__ __align__(16) __nv_bfloat16 g_WDl[18*8192];

__device__ __forceinline__ unsigned smem_u32(const void* p){
    unsigned r;
    asm("{.reg .u64 t; cvta.to.shared.u64 t, %1; cvt.u32.u64 %0, t;}" : "=r"(r) : "l"(p));
    return r;
}
__device__ __forceinline__ void ldsm4(unsigned* r, unsigned a){
    asm volatile("ldmatrix.sync.aligned.m8n8.x4.shared.b16 {%0,%1,%2,%3}, [%4];"
        : "=r"(r[0]),"=r"(r[1]),"=r"(r[2]),"=r"(r[3]) : "r"(a));
}
__device__ __forceinline__ void mma16816(float* d, const unsigned* a, unsigned b0, unsigned b1){
    asm volatile("mma.sync.aligned.m16n8k16.row.col.f32.bf16.bf16.f32 "
        "{%0,%1,%2,%3}, {%4,%5,%6,%7}, {%8,%9}, {%0,%1,%2,%3};"
        : "+f"(d[0]),"+f"(d[1]),"+f"(d[2]),"+f"(d[3])
        : "r"(a[0]),"r"(a[1]),"r"(a[2]),"r"(a[3]), "r"(b0),"r"(b1));
}

// ---------------- FFT over W ---------------------------------------------
__global__ void fft_rows_k(const float* __restrict__ x) {
    __shared__ float2 sm[256];
    __shared__ float2 tw[128];
    int bid = blockIdx.x;
    int m = bid & (Hh-1), c = (bid >> 7) & (Cc-1), b = bid >> 14;
    int tid = threadIdx.x;
    float ang = -2.0f*PI_F*(float)tid/256.0f;
    tw[tid] = make_float2(cosf(ang), sinf(ang));
    const float* row = x + ((size_t)(b*Cc + c)*Hh + m)*Ww;
    for (int i = tid; i < 256; i += 128)
        sm[__brev(i) >> 24] = make_float2(row[i], 0.0f);
    __syncthreads();
#pragma unroll
    for (int s = 1; s <= 8; s++) {
        int half = 1 << (s-1);
        int pos = tid & (half-1);
        int i0 = ((tid >> (s-1)) << s) | pos, i1 = i0 + half;
        float2 w = tw[pos << (8-s)];
        float2 a = sm[i0], bv = sm[i1];
        float2 t = make_float2(bv.x*w.x - bv.y*w.y, bv.x*w.y + bv.y*w.x);
        sm[i0] = make_float2(a.x + t.x, a.y + t.y);
        sm[i1] = make_float2(a.x - t.x, a.y - t.y);
        __syncthreads();
    }
    g_R[((size_t)(b*KWF + tid)*Cc + c)*Hh + m] = sm[tid];
    if (tid == 0)
        g_R[((size_t)(b*KWF + 128)*Cc + c)*Hh + m] = sm[128];
}

// ---------------- FFT over H ---------------------------------------------
__global__ void fft_cols_k(void) {
    __shared__ float2 sm[2][128];
    __shared__ float2 tw[64];
    __shared__ float  mg[128];
    int bid = blockIdx.x;
    int cp = bid & 63, kw = (bid >> 6) % KWF, b = bid / (64*KWF);
    int tid = threadIdx.x, lane = tid & 63, f = tid >> 6;
    int c = cp*2 + f;
    if (tid < 64) {
        float ang = -2.0f*PI_F*(float)tid/128.0f;
        tw[tid] = make_float2(cosf(ang), sinf(ang));
    }
    const float2* base = g_R + (size_t)(b*KWF + kw)*Cc*Hh + c*Hh;
#pragma unroll
    for (int i = lane; i < 128; i += 64)
        sm[f][__brev(i) >> 25] = base[i];
    __syncthreads();
#pragma unroll
    for (int s = 1; s <= 7; s++) {
        int half = 1 << (s-1);
        int pos = lane & (half-1);
        int i0 = ((lane >> (s-1)) << s) | pos, i1 = i0 + half;
        float2 w = tw[pos << (7-s)];
        float2 a = sm[f][i0], bv = sm[f][i1];
        float2 t = make_float2(bv.x*w.x - bv.y*w.y, bv.x*w.y + bv.y*w.x);
        sm[f][i0] = make_float2(a.x + t.x, a.y + t.y);
        sm[f][i1] = make_float2(a.x - t.x, a.y - t.y);
        __syncthreads();
    }
    if (f == 0)
        for (int i = lane; i < 128; i += 64) {
            float2 X = sm[0][i];
            mg[i] = sqrtf(X.x*X.x + X.y*X.y);
        }
    __syncthreads();
    if (f == 1)
        for (int i = lane; i < 128; i += 64) {
            float2 X = sm[1][i];
            g_part[(size_t)bid*128 + i] = mg[i] + sqrtf(X.x*X.x + X.y*X.y);
        }
}

__global__ void reduce_feh_k(void) {
    int bid = blockIdx.x;
    int kw = bid % KWF, b = bid / KWF;
    int kh = threadIdx.x;
    float s = 0.0f;
    const float* p = g_part + (size_t)bid*64*128 + kh;
#pragma unroll 8
    for (int cp = 0; cp < 64; cp++) s += p[cp*128];
    g_feh[(size_t)(b*Hh + kh)*KWF + kw] = s * (1.0f/(128.0f*sqrtf((float)HW)));
}

__global__ void resize_fe_k(void) {
    int idx = blockIdx.x*blockDim.x + threadIdx.x;
    if (idx >= Bb*HW) return;
    int w = idx & (Ww-1), h = (idx >> 8) & (Hh-1), b = idx >> 15;
    float px = ((float)w + 0.5f)*(129.0f/256.0f) - 0.5f;
    float x0f = floorf(px);
    float f = px - x0f;
    int x0 = min(max((int)x0f, 0), 128), x1 = min(max((int)x0f + 1, 0), 128);
    const float* r = g_feh + (size_t)(b*Hh + h)*KWF;
    g_fe[idx] = r[x0]*(1.0f-f) + r[x1]*f;
}

// ---------------- transpose + bf16 hi/lo split ---------------------------
__global__ void transpose_k(const float* __restrict__ x) {
    __shared__ float t[32][33];
    int b = blockIdx.z, p0 = blockIdx.x*32, c0 = blockIdx.y*32;
    int tx = threadIdx.x, ty = threadIdx.y;
#pragma unroll
    for (int j = 0; j < 4; j++)
        t[ty + j*8][tx] = x[(size_t)(b*Cc + c0 + ty + j*8)*HW + p0 + tx];
    __syncthreads();
#pragma unroll
    for (int j = 0; j < 4; j++) {
        float v = t[tx][ty + j*8];
        size_t o = (size_t)(b*HW + p0 + ty + j*8)*Cc + c0 + tx;
        g_xT[o] = v;
        __nv_bfloat16 hb = __float2bfloat16(v);
        g_xbh[o] = hb;
        g_xbl[o] = __float2bfloat16(v - __bfloat162float(hb));
    }
}

// ---------------- weight prep: [chunk][co][64] bf16 hi/lo ----------------
__global__ void wprep_k(const float* __restrict__ bw) {
    int idx = blockIdx.x*blockDim.x + threadIdx.x;
    if (idx >= 18*8192) return;
    int c = idx >> 13, r = idx & 8191;
    int co = r >> 6, k = r & 63;
    int kk = c >> 1, ci = (c & 1)*64 + k;
    float v = bw[(size_t)(co*Cc + ci)*9 + kk];
    __nv_bfloat16 hb = __float2bfloat16(v);
    g_WBh[idx] = hb;
    g_WBl[idx] = __float2bfloat16(v - __bfloat162float(hb));
}
__global__ void wprepD_k(const float* __restrict__ dw) {
    int idx = blockIdx.x*blockDim.x + threadIdx.x;
    if (idx >= 18*8192) return;
    int c = idx >> 13, r = idx & 8191;
    int co = r >> 6, k = r & 63;
    int kk = c >> 1, ci = (c & 1)*64 + k;
    float v = dw[(size_t)(co*Cc + ci)*9 + kk];
    __nv_bfloat16 hb = __float2bfloat16(v);
    g_WDh[idx] = hb;
    g_WDl[idx] = __float2bfloat16(v - __bfloat162float(hb));
}

// ---------------- mma.sync base conv: 128co x 128px per CTA --------------
__global__ void __launch_bounds__(256) conv_mma(const float* __restrict__ bias) {
    extern __shared__ __align__(16) unsigned char dsm[];
    __nv_bfloat16* Ah = (__nv_bfloat16*)dsm;
    __nv_bfloat16* Al = Ah + 128*ASTR;
    __nv_bfloat16* Bh = Al + 128*ASTR;
    __nv_bfloat16* Bl = Bh + 128*ASTR;
    int tid = threadIdx.x;
    int wid = tid >> 5, lane = tid & 31;
    int mw = wid & 1, nw = wid >> 1;
    int co0 = mw*64, pxo = nw*32;
    int blk = blockIdx.x;
    int b = blk >> 8;
    int px0 = (blk & 255) * 128;
    int h = px0 >> 8, w0 = px0 & 255;
    int r15 = lane & 15, r16 = (lane >> 4)*8;

    float acc[4][4][4];
#pragma unroll
    for (int mf = 0; mf < 4; mf++)
#pragma unroll
        for (int nf = 0; nf < 4; nf++)
#pragma unroll
            for (int q = 0; q < 4; q++) acc[mf][nf][q] = 0.0f;

    for (int c = 0; c < 18; c++) {
        int kk = c >> 1;
        int dy = kk/3 - 1, dx = kk%3 - 1;
        int ci0 = (c & 1)*64;
        __syncthreads();
        for (int i = tid; i < 2048; i += 256) {
            int buf = i >> 10, idx = i & 1023;
            int row = idx >> 3, seg = idx & 7;
            const float4* src = (const float4*)((buf ? g_WBl : g_WBh) + (size_t)c*8192 + row*64) + seg;
            *((float4*)((buf ? Al : Ah) + row*ASTR) + seg) = *src;
        }
        int sh = h + dy;
        for (int i = tid; i < 2048; i += 256) {
            int buf = i >> 10, idx = i & 1023;
            int p = idx >> 3, seg = idx & 7;
            int sw = w0 + p + dx;
            float4 v = make_float4(0.f,0.f,0.f,0.f);
            if (sw >= 0 && sw < Ww && sh >= 0 && sh < Hh)
                v = *((const float4*)((buf ? g_xbl : g_xbh) +
                      ((size_t)(b*HW) + sh*Ww + sw)*Cc + ci0) + seg);
            *((float4*)((buf ? Bl : Bh) + p*ASTR) + seg) = v;
        }
        __syncthreads();
#pragma unroll
        for (int ks = 0; ks < 4; ks++) {
            unsigned bh[2][4], bl[2][4];
#pragma unroll
            for (int nh = 0; nh < 2; nh++) {
                ldsm4(bh[nh], smem_u32(Bh + (pxo + nh*16 + r15)*ASTR + ks*16 + r16));
                ldsm4(bl[nh], smem_u32(Bl + (pxo + nh*16 + r15)*ASTR + ks*16 + r16));
            }
#pragma unroll
            for (int mf = 0; mf < 4; mf++) {
                unsigned ah[4], al[4];
                ldsm4(ah, smem_u32(Ah + (co0 + mf*16 + r15)*ASTR + ks*16 + r16));
                ldsm4(al, smem_u32(Al + (co0 + mf*16 + r15)*ASTR + ks*16 + r16));
#pragma unroll
                for (int nf = 0; nf < 4; nf++) {
                    int nh = nf >> 1, sel = nf & 1;
                    unsigned b0h = bh[nh][sel], b1h = bh[nh][sel+2];
                    unsigned b0l = bl[nh][sel], b1l = bl[nh][sel+2];
                    mma16816(acc[mf][nf], ah, b0h, b1h);
                    mma16816(acc[mf][nf], ah, b0l, b1l);
                    mma16816(acc[mf][nf], al, b0h, b1h);
                }
            }
        }
    }
    int gid = lane >> 2, t4 = lane & 3;
#pragma unroll
    for (int mf = 0; mf < 4; mf++) {
#pragma unroll
        for (int nf = 0; nf < 4; nf++) {
            int co = co0 + mf*16 + gid;
            int px = px0 + pxo + nf*8 + t4*2;
            float* d = acc[mf][nf];
            *(float2*)(g_ybase + (size_t)(b*Cc + co  )*HW + px) =
                make_float2(d[0] + bias[co],   d[1] + bias[co]);
            *(float2*)(g_ybase + (size_t)(b*Cc + co+8)*HW + px) =
                make_float2(d[2] + bias[co+8], d[3] + bias[co+8]);
        }
    }
}

// ---------------- mma.sync deform GEMM + blend: 128co x 128px ------------
__global__ void __launch_bounds__(256) deform_mma(
        const float* __restrict__ defb, float* __restrict__ out) {
    extern __shared__ __align__(16) unsigned char dsm[];
    __nv_bfloat16* Ah = (__nv_bfloat16*)dsm;
    __nv_bfloat16* Al = Ah + 128*ASTR;
    __nv_bfloat16* Bh = Al + 128*ASTR;
    __nv_bfloat16* Bl = Bh + 128*ASTR;
    __shared__ int   sC[4][128];        // cx0, cx1, cy0, cy1
    __shared__ float sWt[4][128];       // w00, w10, w01, w11
    int tid = threadIdx.x;
    int wid = tid >> 5, lane = tid & 31;
    int mw = wid & 1, nw = wid >> 1;
    int co0 = mw*64, pxo = nw*32;
    int blk = blockIdx.x;
    int b = blk >> 8;
    int px0 = (blk & 255) * 128;
    int r15 = lane & 15, r16 = (lane >> 4)*8;

    float acc[4][4][4];
#pragma unroll
    for (int mf = 0; mf < 4; mf++)
#pragma unroll
        for (int nf = 0; nf < 4; nf++)
#pragma unroll
            for (int q = 0; q < 4; q++) acc[mf][nf][q] = 0.0f;

    for (int c = 0; c < 18; c++) {
        int kk = c >> 1;
        int ci0 = (c & 1)*64;
        __syncthreads();
        if ((c & 1) == 0 && tid < 128) {
            int pp = px0 + tid;
            int hh = pp >> 8, ww = pp & (Ww-1);
            float fpx = (float)ww + g_off[(size_t)(b*18 + 2*kk    )*HW + pp];
            float fpy = (float)hh + g_off[(size_t)(b*18 + 2*kk + 1)*HW + pp];
            float fx0 = floorf(fpx), fy0 = floorf(fpy);
            int X0 = (int)fx0, Y0 = (int)fy0;
            float fx = fpx - fx0, fy = fpy - fy0;
            float w00 = (1.0f-fx)*(1.0f-fy), w10 = fx*(1.0f-fy);
            float w01 = (1.0f-fx)*fy,        w11 = fx*fy;
            if (X0   < 0 || X0   >= Ww) { w00 = 0.0f; w01 = 0.0f; }
            if (X0+1 < 0 || X0+1 >= Ww) { w10 = 0.0f; w11 = 0.0f; }
            if (Y0   < 0 || Y0   >= Hh) { w00 = 0.0f; w10 = 0.0f; }
            if (Y0+1 < 0 || Y0+1 >= Hh) { w01 = 0.0f; w11 = 0.0f; }
            sC[0][tid] = min(max(X0,   0), Ww-1);
            sC[1][tid] = min(max(X0+1, 0), Ww-1);
            sC[2][tid] = min(max(Y0,   0), Hh-1);
            sC[3][tid] = min(max(Y0+1, 0), Hh-1);
            sWt[0][tid] = w00; sWt[1][tid] = w10; sWt[2][tid] = w01; sWt[3][tid] = w11;
        }
        __syncthreads();
        // A: deform weights
        for (int i = tid; i < 2048; i += 256) {
            int buf = i >> 10, idx = i & 1023;
            int row = idx >> 3, seg = idx & 7;
            const float4* src = (const float4*)((buf ? g_WDl : g_WDh) + (size_t)c*8192 + row*64) + seg;
            *((float4*)((buf ? Al : Ah) + row*ASTR) + seg) = *src;
        }
        // B: bilinear sample 128px x 64ci, fp32 -> hi/lo bf16
        for (int i = tid; i < 2048; i += 256) {
            int p = i >> 4, g = i & 15;
            int cx0 = sC[0][p], cx1 = sC[1][p], cy0 = sC[2][p], cy1 = sC[3][p];
            float w00 = sWt[0][p], w10 = sWt[1][p], w01 = sWt[2][p], w11 = sWt[3][p];
            size_t base = (size_t)(b*HW)*Cc + (size_t)(ci0 + g*4);
            float4 a00 = *(const float4*)(g_xT + base + (size_t)(cy0*Ww + cx0)*Cc);
            float4 a10 = *(const float4*)(g_xT + base + (size_t)(cy0*Ww + cx1)*Cc);
            float4 a01 = *(const float4*)(g_xT + base + (size_t)(cy1*Ww + cx0)*Cc);
            float4 a11 = *(const float4*)(g_xT + base + (size_t)(cy1*Ww + cx1)*Cc);
            float4 r;
            r.x = w00*a00.x + w10*a10.x + w01*a01.x + w11*a11.x;
            r.y = w00*a00.y + w10*a10.y + w01*a01.y + w11*a11.y;
            r.z = w00*a00.z + w10*a10.z + w01*a01.z + w11*a11.z;
            r.w = w00*a00.w + w10*a10.w + w01*a01.w + w11*a11.w;
            __nv_bfloat16 h0 = __float2bfloat16(r.x), h1 = __float2bfloat16(r.y);
            __nv_bfloat16 h2 = __float2bfloat16(r.z), h3 = __float2bfloat16(r.w);
            __nv_bfloat162* dh = (__nv_bfloat162*)(Bh + p*ASTR + g*4);
            dh[0] = __nv_bfloat162(h0, h1);
            dh[1] = __nv_bfloat162(h2, h3);
            __nv_bfloat162* dl = (__nv_bfloat162*)(Bl + p*ASTR + g*4);
            dl[0] = __nv_bfloat162(__float2bfloat16(r.x - __bfloat162float(h0)),
                                   __float2bfloat16(r.y - __bfloat162float(h1)));
            dl[1] = __nv_bfloat162(__float2bfloat16(r.z - __bfloat162float(h2)),
                                   __float2bfloat16(r.w - __bfloat162float(h3)));
        }
        __syncthreads();
#pragma unroll
        for (int ks = 0; ks < 4; ks++) {
            unsigned bh[2][4], bl[2][4];
#pragma unroll
            for (int nh = 0; nh < 2; nh++) {
                ldsm4(bh[nh], smem_u32(Bh + (pxo + nh*16 + r15)*ASTR + ks*16 + r16));
                ldsm4(bl[nh], smem_u32(Bl + (pxo + nh*16 + r15)*ASTR + ks*16 + r16));
            }
#pragma unroll
            for (int mf = 0; mf < 4; mf++) {
                unsigned ah[4], al[4];
                ldsm4(ah, smem_u32(Ah + (co0 + mf*16 + r15)*ASTR + ks*16 + r16));
                ldsm4(al, smem_u32(Al + (co0 + mf*16 + r15)*ASTR + ks*16 + r16));
#pragma unroll
                for (int nf = 0; nf < 4; nf++) {
                    int nh = nf >> 1, sel = nf & 1;
                    unsigned b0h = bh[nh][sel], b1h = bh[nh][sel+2];
                    unsigned b0l = bl[nh][sel], b1l = bl[nh][sel+2];
                    mma16816(acc[mf][nf], ah, b0h, b1h);
                    mma16816(acc[mf][nf], ah, b0l, b1l);
                    mma16816(acc[mf][nf], al, b0h, b1h);
                }
            }
        }
    }
    // epilogue: blend with gate / ybase
    int gid = lane >> 2, t4 = lane & 3;
#pragma unroll
    for (int mf = 0; mf < 4; mf++) {
#pragma unroll
        for (int nf = 0; nf < 4; nf++) {
            int co = co0 + mf*16 + gid;
            int px = px0 + pxo + nf*8 + t4*2;
            float* d = acc[mf][nf];
            float g0 = g_gate[(size_t)b*HW + px], g1 = g_gate[(size_t)b*HW + px + 1];
            float bs0 = defb[co], bs8 = defb[co+8];
            const float* yb0 = g_ybase + (size_t)(b*Cc + co  )*HW + px;
            const float* yb8 = g_ybase + (size_t)(b*Cc + co+8)*HW + px;
            *(float2*)(out + (size_t)(b*Cc + co  )*HW + px) = make_float2(
                (1.0f-g0)*yb0[0] + g0*(d[0]+bs0), (1.0f-g1)*yb0[1] + g1*(d[1]+bs0));
            *(float2*)(out + (size_t)(b*Cc + co+8)*HW + px) = make_float2(
                (1.0f-g0)*yb8[0] + g0*(d[2]+bs8), (1.0f-g1)*yb8[1] + g1*(d[3]+bs8));
        }
    }
}

// ---------------- fused aux weights --------------------------------------
__global__ void wfuse_k(const float* __restrict__ ow, const float* __restrict__ ob,
                        const float* __restrict__ gw, const float* __restrict__ gb) {
    int idx = blockIdx.x*blockDim.x + threadIdx.x;
    if (idx < 84*AUXC*9) {
        int co = idx / (AUXC*9), r = idx % (AUXC*9);
        g_wF[idx] = (co < 18) ? ow[(size_t)co*AUXC*9 + r] : gw[(size_t)(co-18)*AUXC*9 + r];
    }
    if (idx < 96) g_bF[idx] = (idx < 18) ? ob[idx] : (idx < 84 ? gb[idx-18] : 0.0f);
}

// ---------------- aux conv (offset 0-17, gate 18-83), scalar -------------
__global__ void __launch_bounds__(256) conv_aux_k(const float* __restrict__ xin) {
    __shared__ float tile[6][34];
    __shared__ float ws[32][9];
    int tid = threadIdx.x;
    int xt = tid & 31, ct = tid >> 5;
    int x0 = blockIdx.x*32, y0 = blockIdx.y*4;
    int b = blockIdx.z / 3;
    int coB = (blockIdx.z % 3)*32;
    float acc[4][4];
#pragma unroll
    for (int j = 0; j < 4; j++)
#pragma unroll
        for (int y = 0; y < 4; y++) acc[j][y] = 0.0f;

    for (int ci = 0; ci < AUXC; ci++) {
        if (tid < 204) {
            int r = tid/34, cc = tid%34;
            int gy = y0 + r - 1, gx = x0 + cc - 1;
            float v = 0.0f;
            if (gy >= 0 && gy < Hh && gx >= 0 && gx < Ww) {
                if (ci < Cc)        v = xin[((size_t)(b*Cc + ci)*Hh + gy)*Ww + gx];
                else if (ci == 128) v = sinf(-PI_F + (2.0f*PI_F/255.0f)*(float)gx);
                else if (ci == 129) v = cosf(-PI_F + (2.0f*PI_F/255.0f)*(float)gx);
                else if (ci == 130) v = sinf(-0.5f*PI_F + (PI_F/127.0f)*(float)gy);
                else if (ci == 131) v = cosf(-0.5f*PI_F + (PI_F/127.0f)*(float)gy);
                else                v = g_fe[(size_t)b*HW + gy*Ww + gx];
            }
            tile[r][cc] = v;
        }
        for (int i = tid; i < 288; i += 256) {
            int co = i/9, tap = i%9;
            int gco = coB + co;
            ws[co][tap] = (gco < 84) ? g_wF[(size_t)(gco*AUXC + ci)*9 + tap] : 0.0f;
        }
        __syncthreads();
        float v[6][3];
#pragma unroll
        for (int r = 0; r < 6; r++)
#pragma unroll
            for (int k = 0; k < 3; k++) v[r][k] = tile[r][xt + k];
#pragma unroll
        for (int j = 0; j < 4; j++) {
            float wr[9];
#pragma unroll
            for (int t = 0; t < 9; t++) wr[t] = ws[ct*4 + j][t];
#pragma unroll
            for (int y = 0; y < 4; y++) {
                float s = acc[j][y];
                s = fmaf(v[y  ][0], wr[0], s); s = fmaf(v[y  ][1], wr[1], s); s = fmaf(v[y  ][2], wr[2], s);
                s = fmaf(v[y+1][0], wr[3], s); s = fmaf(v[y+1][1], wr[4], s); s = fmaf(v[y+1][2], wr[5], s);
                s = fmaf(v[y+2][0], wr[6], s); s = fmaf(v[y+2][1], wr[7], s); s = fmaf(v[y+2][2], wr[8], s);
                acc[j][y] = s;
            }
        }
        __syncthreads();
    }
#pragma unroll
    for (int j = 0; j < 4; j++) {
        int co = coB + ct*4 + j;
        if (co < 84) {
            float bs = g_bF[co];
            float* op;
            bool relu = false;
            if (co < 18) op = g_off + (size_t)(b*18 + co)*HW;
            else { op = g_gbuf + (size_t)(b*66 + co - 18)*HW; relu = true; }
#pragma unroll
            for (int y = 0; y < 4; y++) {
                float o = acc[j][y] + bs;
                if (relu) o = fmaxf(o, 0.0f);
                op[(size_t)(y0 + y)*Ww + x0 + xt] = o;
            }
        }
    }
}

__global__ void gate1x1_k(const float* __restrict__ w2, const float* __restrict__ b2) {
    int idx = blockIdx.x*blockDim.x + threadIdx.x;
    if (idx >= Bb*HW) return;
    int b = idx >> 15, p = idx & (HW-1);
    float s = b2[0];
#pragma unroll 6
    for (int c = 0; c < 66; c++)
        s = fmaf(g_gbuf[(size_t)(b*66 + c)*HW + p], w2[c], s);
    g_gate[idx] = 1.0f / (1.0f + expf(-s));
}

// ---------------- host launcher ------------------------------------------
extern "C" void kernel_launch(void* const* d_in, const int* in_sizes, int n_in,
                              void* d_out, int out_size) {
    const float* x      = (const float*)d_in[0];
    const float* off_w  = (const float*)d_in[1];
    const float* off_b  = (const float*)d_in[2];
    const float* gw1    = (const float*)d_in[3];
    const float* gb1    = (const float*)d_in[4];
    const float* gw2    = (const float*)d_in[5];
    const float* gb2    = (const float*)d_in[6];
    const float* base_w = (const float*)d_in[7];
    const float* base_b = (const float*)d_in[8];
    const float* def_w  = (const float*)d_in[9];
    const float* def_b  = (const float*)d_in[10];
    float* out = (float*)d_out;

    const int MMA_SMEM = 4*128*ASTR*2;     // 90112 bytes
    cudaFuncSetAttribute(conv_mma,   cudaFuncAttributeMaxDynamicSharedMemorySize, MMA_SMEM);
    cudaFuncSetAttribute(deform_mma, cudaFuncAttributeMaxDynamicSharedMemorySize, MMA_SMEM);

    fft_rows_k<<<Bb*Cc*Hh, 128>>>(x);
    fft_cols_k<<<Bb*KWF*64, 128>>>();
    reduce_feh_k<<<Bb*KWF, 128>>>();
    transpose_k<<<dim3(HW/32, Cc/32, Bb), dim3(32, 8)>>>(x);
    wprep_k<<<(18*8192 + 255)/256, 256>>>(base_w);
    wprepD_k<<<(18*8192 + 255)/256, 256>>>(def_w);
    conv_mma<<<Bb*256, 256, MMA_SMEM>>>(base_b);
    resize_fe_k<<<(Bb*HW + 255)/256, 256>>>();
    wfuse_k<<<(84*AUXC*9 + 255)/256, 256>>>(off_w, off_b, gw1, gb1);
    conv_aux_k<<<dim3(8, 32, Bb*3), 256>>>(x);
    gate1x1_k<<<(Bb*HW + 255)/256, 256>>>(gw2, gb2);
    deform_mma<<<Bb*256, 256, MMA_SMEM>>>(def_b, out);
}

// round 12
// speedup vs baseline: 2.4384x; 1.3629x over previous
#include <cuda_runtime.h>
#include <cuda_bf16.h>
#include <math.h>

#define PI_F 3.14159265358979323846f
#define Bb   2
#define Cc   128
#define Hh   128
#define Ww   256
#define HW   32768
#define AUXC 133
#define KWF  129
#define ASTR 88

__device__ float2 g_R[Bb*KWF*Cc*Hh];
__device__ float  g_part[Bb*KWF*64*128];
__device__ float  g_feh[Bb*Hh*KWF];
__device__ float  g_fe[Bb*HW];
__device__ float  g_off[Bb*18*HW];
__device__ float  g_gbuf[Bb*66*HW];
__device__ float  g_gate[Bb*HW];
__device__ float  g_ybase[Bb*Cc*HW];
__device__ float  g_xT[Bb*HW*Cc];
__device__ float  g_bF[96];
__device__ __align__(16) __nv_bfloat16 g_xbh[(size_t)Bb*HW*Cc];
__device__ __align__(16) __nv_bfloat16 g_xbl[(size_t)Bb*HW*Cc];
__device__ __align__(16) __nv_bfloat16 g_ath[(size_t)Bb*HW*16];   // aux tail NHWC
__device__ __align__(16) __nv_bfloat16 g_atl[(size_t)Bb*HW*16];
__device__ __align__(16) __nv_bfloat16 g_WBh[18*8192];
__device__ __align__(16) __nv_bfloat16 g_WBl[18*8192];
__device__ __align__(16) __nv_bfloat16 g_WDh[18*8192];
__device__ __align__(16) __nv_bfloat16 g_WDl[18*8192];
__device__ __align__(16) __nv_bfloat16 g_WAh[27*8192];
__device__ __align__(16) __nv_bfloat16 g_WAl[27*8192];

__device__ __forceinline__ unsigned smem_u32(const void* p){
    unsigned r;
    asm("{.reg .u64 t; cvta.to.shared.u64 t, %1; cvt.u32.u64 %0, t;}" : "=r"(r) : "l"(p));
    return r;
}
__device__ __forceinline__ void ldsm4(unsigned* r, unsigned a){
    asm volatile("ldmatrix.sync.aligned.m8n8.x4.shared.b16 {%0,%1,%2,%3}, [%4];"
        : "=r"(r[0]),"=r"(r[1]),"=r"(r[2]),"=r"(r[3]) : "r"(a));
}
__device__ __forceinline__ void mma16816(float* d, const unsigned* a, unsigned b0, unsigned b1){
    asm volatile("mma.sync.aligned.m16n8k16.row.col.f32.bf16.bf16.f32 "
        "{%0,%1,%2,%3}, {%4,%5,%6,%7}, {%8,%9}, {%0,%1,%2,%3};"
        : "+f"(d[0]),"+f"(d[1]),"+f"(d[2]),"+f"(d[3])
        : "r"(a[0]),"r"(a[1]),"r"(a[2]),"r"(a[3]), "r"(b0),"r"(b1));
}
__device__ __forceinline__ void bsplit2(float v, __nv_bfloat16& h, __nv_bfloat16& l){
    h = __float2bfloat16(v);
    l = __float2bfloat16(v - __bfloat162float(h));
}

// ---------------- FFT over W ---------------------------------------------
__global__ void fft_rows_k(const float* __restrict__ x) {
    __shared__ float2 sm[256];
    __shared__ float2 tw[128];
    int bid = blockIdx.x;
    int m = bid & (Hh-1), c = (bid >> 7) & (Cc-1), b = bid >> 14;
    int tid = threadIdx.x;
    float ang = -2.0f*PI_F*(float)tid/256.0f;
    tw[tid] = make_float2(cosf(ang), sinf(ang));
    const float* row = x + ((size_t)(b*Cc + c)*Hh + m)*Ww;
    for (int i = tid; i < 256; i += 128)
        sm[__brev(i) >> 24] = make_float2(row[i], 0.0f);
    __syncthreads();
#pragma unroll
    for (int s = 1; s <= 8; s++) {
        int half = 1 << (s-1);
        int pos = tid & (half-1);
        int i0 = ((tid >> (s-1)) << s) | pos, i1 = i0 + half;
        float2 w = tw[pos << (8-s)];
        float2 a = sm[i0], bv = sm[i1];
        float2 t = make_float2(bv.x*w.x - bv.y*w.y, bv.x*w.y + bv.y*w.x);
        sm[i0] = make_float2(a.x + t.x, a.y + t.y);
        sm[i1] = make_float2(a.x - t.x, a.y - t.y);
        __syncthreads();
    }
    g_R[((size_t)(b*KWF + tid)*Cc + c)*Hh + m] = sm[tid];
    if (tid == 0)
        g_R[((size_t)(b*KWF + 128)*Cc + c)*Hh + m] = sm[128];
}

// ---------------- FFT over H ---------------------------------------------
__global__ void fft_cols_k(void) {
    __shared__ float2 sm[2][128];
    __shared__ float2 tw[64];
    __shared__ float  mg[128];
    int bid = blockIdx.x;
    int cp = bid & 63, kw = (bid >> 6) % KWF, b = bid / (64*KWF);
    int tid = threadIdx.x, lane = tid & 63, f = tid >> 6;
    int c = cp*2 + f;
    if (tid < 64) {
        float ang = -2.0f*PI_F*(float)tid/128.0f;
        tw[tid] = make_float2(cosf(ang), sinf(ang));
    }
    const float2* base = g_R + (size_t)(b*KWF + kw)*Cc*Hh + c*Hh;
#pragma unroll
    for (int i = lane; i < 128; i += 64)
        sm[f][__brev(i) >> 25] = base[i];
    __syncthreads();
#pragma unroll
    for (int s = 1; s <= 7; s++) {
        int half = 1 << (s-1);
        int pos = lane & (half-1);
        int i0 = ((lane >> (s-1)) << s) | pos, i1 = i0 + half;
        float2 w = tw[pos << (7-s)];
        float2 a = sm[f][i0], bv = sm[f][i1];
        float2 t = make_float2(bv.x*w.x - bv.y*w.y, bv.x*w.y + bv.y*w.x);
        sm[f][i0] = make_float2(a.x + t.x, a.y + t.y);
        sm[f][i1] = make_float2(a.x - t.x, a.y - t.y);
        __syncthreads();
    }
    if (f == 0)
        for (int i = lane; i < 128; i += 64) {
            float2 X = sm[0][i];
            mg[i] = sqrtf(X.x*X.x + X.y*X.y);
        }
    __syncthreads();
    if (f == 1)
        for (int i = lane; i < 128; i += 64) {
            float2 X = sm[1][i];
            g_part[(size_t)bid*128 + i] = mg[i] + sqrtf(X.x*X.x + X.y*X.y);
        }
}

__global__ void reduce_feh_k(void) {
    int bid = blockIdx.x;
    int kw = bid % KWF, b = bid / KWF;
    int kh = threadIdx.x;
    float s = 0.0f;
    const float* p = g_part + (size_t)bid*64*128 + kh;
#pragma unroll 8
    for (int cp = 0; cp < 64; cp++) s += p[cp*128];
    g_feh[(size_t)(b*Hh + kh)*KWF + kw] = s * (1.0f/(128.0f*sqrtf((float)HW)));
}

__global__ void resize_fe_k(void) {
    int idx = blockIdx.x*blockDim.x + threadIdx.x;
    if (idx >= Bb*HW) return;
    int w = idx & (Ww-1), h = (idx >> 8) & (Hh-1), b = idx >> 15;
    float px = ((float)w + 0.5f)*(129.0f/256.0f) - 0.5f;
    float x0f = floorf(px);
    float f = px - x0f;
    int x0 = min(max((int)x0f, 0), 128), x1 = min(max((int)x0f + 1, 0), 128);
    const float* r = g_feh + (size_t)(b*Hh + h)*KWF;
    g_fe[idx] = r[x0]*(1.0f-f) + r[x1]*f;
}

// ---------------- aux tail: 16 NHWC channels (coords, fe, pad) -----------
__global__ void auxtail_k(void) {
    int idx = blockIdx.x*blockDim.x + threadIdx.x;
    if (idx >= Bb*HW) return;
    int w = idx & (Ww-1), h = (idx >> 8) & (Hh-1);
    float th = -PI_F + (2.0f*PI_F/255.0f)*(float)w;
    float ph = -0.5f*PI_F + (PI_F/127.0f)*(float)h;
    float v[16] = {sinf(th), cosf(th), sinf(ph), cosf(ph), g_fe[idx],
                   0,0,0,0,0,0,0,0,0,0,0};
    __nv_bfloat16* oh = g_ath + (size_t)idx*16;
    __nv_bfloat16* ol = g_atl + (size_t)idx*16;
#pragma unroll
    for (int k = 0; k < 16; k++) {
        __nv_bfloat16 hb, lb; bsplit2(v[k], hb, lb);
        oh[k] = hb; ol[k] = lb;
    }
}

// ---------------- transpose + bf16 hi/lo split ---------------------------
__global__ void transpose_k(const float* __restrict__ x) {
    __shared__ float t[32][33];
    int b = blockIdx.z, p0 = blockIdx.x*32, c0 = blockIdx.y*32;
    int tx = threadIdx.x, ty = threadIdx.y;
#pragma unroll
    for (int j = 0; j < 4; j++)
        t[ty + j*8][tx] = x[(size_t)(b*Cc + c0 + ty + j*8)*HW + p0 + tx];
    __syncthreads();
#pragma unroll
    for (int j = 0; j < 4; j++) {
        float v = t[tx][ty + j*8];
        size_t o = (size_t)(b*HW + p0 + ty + j*8)*Cc + c0 + tx;
        g_xT[o] = v;
        __nv_bfloat16 hb, lb; bsplit2(v, hb, lb);
        g_xbh[o] = hb; g_xbl[o] = lb;
    }
}

// ---------------- weight preps -------------------------------------------
__global__ void wprep_k(const float* __restrict__ bw) {
    int idx = blockIdx.x*blockDim.x + threadIdx.x;
    if (idx >= 18*8192) return;
    int c = idx >> 13, r = idx & 8191;
    int co = r >> 6, k = r & 63;
    int kk = c >> 1, ci = (c & 1)*64 + k;
    float v = bw[(size_t)(co*Cc + ci)*9 + kk];
    __nv_bfloat16 hb, lb; bsplit2(v, hb, lb);
    g_WBh[idx] = hb; g_WBl[idx] = lb;
}
__global__ void wprepD_k(const float* __restrict__ dw) {
    int idx = blockIdx.x*blockDim.x + threadIdx.x;
    if (idx >= 18*8192) return;
    int c = idx >> 13, r = idx & 8191;
    int co = r >> 6, k = r & 63;
    int kk = c >> 1, ci = (c & 1)*64 + k;
    float v = dw[(size_t)(co*Cc + ci)*9 + kk];
    __nv_bfloat16 hb, lb; bsplit2(v, hb, lb);
    g_WDh[idx] = hb; g_WDl[idx] = lb;
}
__global__ void wprepA_k(const float* __restrict__ ow, const float* __restrict__ ob,
                         const float* __restrict__ gw, const float* __restrict__ gb) {
    int idx = blockIdx.x*blockDim.x + threadIdx.x;
    if (idx < 96) g_bF[idx] = (idx < 18) ? ob[idx] : (idx < 84 ? gb[idx-18] : 0.0f);
    if (idx >= 27*8192) return;
    int c = idx >> 13, r = idx & 8191;
    int co = r >> 6, k = r & 63;
    int tap = c / 3, sub = c % 3;
    int ci = sub*64 + k;
    float v = 0.0f;
    if (co < 84 && ci < AUXC)
        v = (co < 18) ? ow[(size_t)(co*AUXC + ci)*9 + tap]
                      : gw[(size_t)((co-18)*AUXC + ci)*9 + tap];
    __nv_bfloat16 hb, lb; bsplit2(v, hb, lb);
    g_WAh[idx] = hb; g_WAl[idx] = lb;
}

// ---------------- mma.sync base conv -------------------------------------
__global__ void __launch_bounds__(256) conv_mma(const float* __restrict__ bias) {
    extern __shared__ __align__(16) unsigned char dsm[];
    __nv_bfloat16* Ah = (__nv_bfloat16*)dsm;
    __nv_bfloat16* Al = Ah + 128*ASTR;
    __nv_bfloat16* Bh = Al + 128*ASTR;
    __nv_bfloat16* Bl = Bh + 128*ASTR;
    int tid = threadIdx.x;
    int wid = tid >> 5, lane = tid & 31;
    int co0 = (wid & 1)*64, pxo = (wid >> 1)*32;
    int blk = blockIdx.x;
    int b = blk >> 8;
    int px0 = (blk & 255) * 128;
    int h = px0 >> 8, w0 = px0 & 255;
    int r15 = lane & 15, r16 = (lane >> 4)*8;

    float acc[4][4][4];
#pragma unroll
    for (int mf = 0; mf < 4; mf++)
#pragma unroll
        for (int nf = 0; nf < 4; nf++)
#pragma unroll
            for (int q = 0; q < 4; q++) acc[mf][nf][q] = 0.0f;

    for (int c = 0; c < 18; c++) {
        int kk = c >> 1;
        int dy = kk/3 - 1, dx = kk%3 - 1;
        int ci0 = (c & 1)*64;
        __syncthreads();
        for (int i = tid; i < 2048; i += 256) {
            int buf = i >> 10, idx = i & 1023;
            int row = idx >> 3, seg = idx & 7;
            *((float4*)((buf ? Al : Ah) + row*ASTR) + seg) =
                *((const float4*)((buf ? g_WBl : g_WBh) + (size_t)c*8192 + row*64) + seg);
        }
        int sh = h + dy;
        for (int i = tid; i < 2048; i += 256) {
            int buf = i >> 10, idx = i & 1023;
            int p = idx >> 3, seg = idx & 7;
            int sw = w0 + p + dx;
            float4 v = make_float4(0.f,0.f,0.f,0.f);
            if (sw >= 0 && sw < Ww && sh >= 0 && sh < Hh)
                v = *((const float4*)((buf ? g_xbl : g_xbh) +
                      ((size_t)(b*HW) + sh*Ww + sw)*Cc + ci0) + seg);
            *((float4*)((buf ? Bl : Bh) + p*ASTR) + seg) = v;
        }
        __syncthreads();
#pragma unroll
        for (int ks = 0; ks < 4; ks++) {
            unsigned bh[2][4], bl[2][4];
#pragma unroll
            for (int nh = 0; nh < 2; nh++) {
                ldsm4(bh[nh], smem_u32(Bh + (pxo + nh*16 + r15)*ASTR + ks*16 + r16));
                ldsm4(bl[nh], smem_u32(Bl + (pxo + nh*16 + r15)*ASTR + ks*16 + r16));
            }
#pragma unroll
            for (int mf = 0; mf < 4; mf++) {
                unsigned ah[4], al[4];
                ldsm4(ah, smem_u32(Ah + (co0 + mf*16 + r15)*ASTR + ks*16 + r16));
                ldsm4(al, smem_u32(Al + (co0 + mf*16 + r15)*ASTR + ks*16 + r16));
#pragma unroll
                for (int nf = 0; nf < 4; nf++) {
                    int nh = nf >> 1, sel = nf & 1;
                    mma16816(acc[mf][nf], ah, bh[nh][sel], bh[nh][sel+2]);
                    mma16816(acc[mf][nf], ah, bl[nh][sel], bl[nh][sel+2]);
                    mma16816(acc[mf][nf], al, bh[nh][sel], bh[nh][sel+2]);
                }
            }
        }
    }
    int gid = lane >> 2, t4 = lane & 3;
#pragma unroll
    for (int mf = 0; mf < 4; mf++) {
#pragma unroll
        for (int nf = 0; nf < 4; nf++) {
            int co = co0 + mf*16 + gid;
            int px = px0 + pxo + nf*8 + t4*2;
            float* d = acc[mf][nf];
            *(float2*)(g_ybase + (size_t)(b*Cc + co  )*HW + px) =
                make_float2(d[0] + bias[co],   d[1] + bias[co]);
            *(float2*)(g_ybase + (size_t)(b*Cc + co+8)*HW + px) =
                make_float2(d[2] + bias[co+8], d[3] + bias[co+8]);
        }
    }
}

// ---------------- mma.sync aux conv (offset+gate) ------------------------
__global__ void __launch_bounds__(256) conv_aux_mma(void) {
    extern __shared__ __align__(16) unsigned char dsm[];
    __nv_bfloat16* Ah = (__nv_bfloat16*)dsm;
    __nv_bfloat16* Al = Ah + 128*ASTR;
    __nv_bfloat16* Bh = Al + 128*ASTR;
    __nv_bfloat16* Bl = Bh + 128*ASTR;
    int tid = threadIdx.x;
    int wid = tid >> 5, lane = tid & 31;
    int co0 = (wid & 1)*64, pxo = (wid >> 1)*32;
    int blk = blockIdx.x;
    int b = blk >> 8;
    int px0 = (blk & 255) * 128;
    int h = px0 >> 8, w0 = px0 & 255;
    int r15 = lane & 15, r16 = (lane >> 4)*8;

    float acc[4][4][4];
#pragma unroll
    for (int mf = 0; mf < 4; mf++)
#pragma unroll
        for (int nf = 0; nf < 4; nf++)
#pragma unroll
            for (int q = 0; q < 4; q++) acc[mf][nf][q] = 0.0f;

    for (int c = 0; c < 27; c++) {
        int tap = c / 3, sub = c - tap*3;
        int dy = tap/3 - 1, dx = tap%3 - 1;
        __syncthreads();
        for (int i = tid; i < 2048; i += 256) {
            int buf = i >> 10, idx = i & 1023;
            int row = idx >> 3, seg = idx & 7;
            *((float4*)((buf ? Al : Ah) + row*ASTR) + seg) =
                *((const float4*)((buf ? g_WAl : g_WAh) + (size_t)c*8192 + row*64) + seg);
        }
        int sh = h + dy;
        if (sub < 2) {
            int ci0 = sub*64;
            for (int i = tid; i < 2048; i += 256) {
                int buf = i >> 10, idx = i & 1023;
                int p = idx >> 3, seg = idx & 7;
                int sw = w0 + p + dx;
                float4 v = make_float4(0.f,0.f,0.f,0.f);
                if (sw >= 0 && sw < Ww && sh >= 0 && sh < Hh)
                    v = *((const float4*)((buf ? g_xbl : g_xbh) +
                          ((size_t)(b*HW) + sh*Ww + sw)*Cc + ci0) + seg);
                *((float4*)((buf ? Bl : Bh) + p*ASTR) + seg) = v;
            }
        } else {
            for (int i = tid; i < 512; i += 256) {
                int buf = i >> 8, idx = i & 255;
                int p = idx >> 1, seg = idx & 1;
                int sw = w0 + p + dx;
                float4 v = make_float4(0.f,0.f,0.f,0.f);
                if (sw >= 0 && sw < Ww && sh >= 0 && sh < Hh)
                    v = *((const float4*)((buf ? g_atl : g_ath) +
                          ((size_t)(b*HW) + sh*Ww + sw)*16) + seg);
                *((float4*)((buf ? Bl : Bh) + p*ASTR) + seg) = v;
            }
        }
        __syncthreads();
        int nks = (sub < 2) ? 4 : 1;
        for (int ks = 0; ks < nks; ks++) {
            unsigned bh[2][4], bl[2][4];
#pragma unroll
            for (int nh = 0; nh < 2; nh++) {
                ldsm4(bh[nh], smem_u32(Bh + (pxo + nh*16 + r15)*ASTR + ks*16 + r16));
                ldsm4(bl[nh], smem_u32(Bl + (pxo + nh*16 + r15)*ASTR + ks*16 + r16));
            }
#pragma unroll
            for (int mf = 0; mf < 4; mf++) {
                unsigned ah[4], al[4];
                ldsm4(ah, smem_u32(Ah + (co0 + mf*16 + r15)*ASTR + ks*16 + r16));
                ldsm4(al, smem_u32(Al + (co0 + mf*16 + r15)*ASTR + ks*16 + r16));
#pragma unroll
                for (int nf = 0; nf < 4; nf++) {
                    int nh = nf >> 1, sel = nf & 1;
                    mma16816(acc[mf][nf], ah, bh[nh][sel], bh[nh][sel+2]);
                    mma16816(acc[mf][nf], ah, bl[nh][sel], bl[nh][sel+2]);
                    mma16816(acc[mf][nf], al, bh[nh][sel], bh[nh][sel+2]);
                }
            }
        }
    }
    int gid = lane >> 2, t4 = lane & 3;
#pragma unroll
    for (int mf = 0; mf < 4; mf++) {
#pragma unroll
        for (int nf = 0; nf < 4; nf++) {
            int px = px0 + pxo + nf*8 + t4*2;
            float* d = acc[mf][nf];
#pragma unroll
            for (int half = 0; half < 2; half++) {
                int co = co0 + mf*16 + gid + half*8;
                float v0 = d[half*2] + g_bF[co], v1 = d[half*2+1] + g_bF[co];
                if (co < 18) {
                    *(float2*)(g_off + (size_t)(b*18 + co)*HW + px) = make_float2(v0, v1);
                } else if (co < 84) {
                    *(float2*)(g_gbuf + (size_t)(b*66 + co - 18)*HW + px) =
                        make_float2(fmaxf(v0, 0.0f), fmaxf(v1, 0.0f));
                }
            }
        }
    }
}

// ---------------- mma.sync deform GEMM + blend ---------------------------
__global__ void __launch_bounds__(256) deform_mma(
        const float* __restrict__ defb, float* __restrict__ out) {
    extern __shared__ __align__(16) unsigned char dsm[];
    __nv_bfloat16* Ah = (__nv_bfloat16*)dsm;
    __nv_bfloat16* Al = Ah + 128*ASTR;
    __nv_bfloat16* Bh = Al + 128*ASTR;
    __nv_bfloat16* Bl = Bh + 128*ASTR;
    __shared__ int   sC[4][128];
    __shared__ float sWt[4][128];
    int tid = threadIdx.x;
    int wid = tid >> 5, lane = tid & 31;
    int co0 = (wid & 1)*64, pxo = (wid >> 1)*32;
    int blk = blockIdx.x;
    int b = blk >> 8;
    int px0 = (blk & 255) * 128;
    int r15 = lane & 15, r16 = (lane >> 4)*8;

    float acc[4][4][4];
#pragma unroll
    for (int mf = 0; mf < 4; mf++)
#pragma unroll
        for (int nf = 0; nf < 4; nf++)
#pragma unroll
            for (int q = 0; q < 4; q++) acc[mf][nf][q] = 0.0f;

    for (int c = 0; c < 18; c++) {
        int kk = c >> 1;
        int ci0 = (c & 1)*64;
        __syncthreads();
        if ((c & 1) == 0 && tid < 128) {
            int pp = px0 + tid;
            int hh = pp >> 8, ww = pp & (Ww-1);
            float fpx = (float)ww + g_off[(size_t)(b*18 + 2*kk    )*HW + pp];
            float fpy = (float)hh + g_off[(size_t)(b*18 + 2*kk + 1)*HW + pp];
            float fx0 = floorf(fpx), fy0 = floorf(fpy);
            int X0 = (int)fx0, Y0 = (int)fy0;
            float fx = fpx - fx0, fy = fpy - fy0;
            float w00 = (1.0f-fx)*(1.0f-fy), w10 = fx*(1.0f-fy);
            float w01 = (1.0f-fx)*fy,        w11 = fx*fy;
            if (X0   < 0 || X0   >= Ww) { w00 = 0.0f; w01 = 0.0f; }
            if (X0+1 < 0 || X0+1 >= Ww) { w10 = 0.0f; w11 = 0.0f; }
            if (Y0   < 0 || Y0   >= Hh) { w00 = 0.0f; w10 = 0.0f; }
            if (Y0+1 < 0 || Y0+1 >= Hh) { w01 = 0.0f; w11 = 0.0f; }
            sC[0][tid] = min(max(X0,   0), Ww-1);
            sC[1][tid] = min(max(X0+1, 0), Ww-1);
            sC[2][tid] = min(max(Y0,   0), Hh-1);
            sC[3][tid] = min(max(Y0+1, 0), Hh-1);
            sWt[0][tid] = w00; sWt[1][tid] = w10; sWt[2][tid] = w01; sWt[3][tid] = w11;
        }
        __syncthreads();
        for (int i = tid; i < 2048; i += 256) {
            int buf = i >> 10, idx = i & 1023;
            int row = idx >> 3, seg = idx & 7;
            *((float4*)((buf ? Al : Ah) + row*ASTR) + seg) =
                *((const float4*)((buf ? g_WDl : g_WDh) + (size_t)c*8192 + row*64) + seg);
        }
        for (int i = tid; i < 2048; i += 256) {
            int p = i >> 4, g = i & 15;
            int cx0 = sC[0][p], cx1 = sC[1][p], cy0 = sC[2][p], cy1 = sC[3][p];
            float w00 = sWt[0][p], w10 = sWt[1][p], w01 = sWt[2][p], w11 = sWt[3][p];
            size_t base = (size_t)(b*HW)*Cc + (size_t)(ci0 + g*4);
            float4 a00 = *(const float4*)(g_xT + base + (size_t)(cy0*Ww + cx0)*Cc);
            float4 a10 = *(const float4*)(g_xT + base + (size_t)(cy0*Ww + cx1)*Cc);
            float4 a01 = *(const float4*)(g_xT + base + (size_t)(cy1*Ww + cx0)*Cc);
            float4 a11 = *(const float4*)(g_xT + base + (size_t)(cy1*Ww + cx1)*Cc);
            float4 r;
            r.x = w00*a00.x + w10*a10.x + w01*a01.x + w11*a11.x;
            r.y = w00*a00.y + w10*a10.y + w01*a01.y + w11*a11.y;
            r.z = w00*a00.z + w10*a10.z + w01*a01.z + w11*a11.z;
            r.w = w00*a00.w + w10*a10.w + w01*a01.w + w11*a11.w;
            __nv_bfloat16 h0, l0, h1, l1, h2, l2, h3, l3;
            bsplit2(r.x, h0, l0); bsplit2(r.y, h1, l1);
            bsplit2(r.z, h2, l2); bsplit2(r.w, h3, l3);
            __nv_bfloat162* dh = (__nv_bfloat162*)(Bh + p*ASTR + g*4);
            dh[0] = __nv_bfloat162(h0, h1); dh[1] = __nv_bfloat162(h2, h3);
            __nv_bfloat162* dl = (__nv_bfloat162*)(Bl + p*ASTR + g*4);
            dl[0] = __nv_bfloat162(l0, l1); dl[1] = __nv_bfloat162(l2, l3);
        }
        __syncthreads();
#pragma unroll
        for (int ks = 0; ks < 4; ks++) {
            unsigned bh[2][4], bl[2][4];
#pragma unroll
            for (int nh = 0; nh < 2; nh++) {
                ldsm4(bh[nh], smem_u32(Bh + (pxo + nh*16 + r15)*ASTR + ks*16 + r16));
                ldsm4(bl[nh], smem_u32(Bl + (pxo + nh*16 + r15)*ASTR + ks*16 + r16));
            }
#pragma unroll
            for (int mf = 0; mf < 4; mf++) {
                unsigned ah[4], al[4];
                ldsm4(ah, smem_u32(Ah + (co0 + mf*16 + r15)*ASTR + ks*16 + r16));
                ldsm4(al, smem_u32(Al + (co0 + mf*16 + r15)*ASTR + ks*16 + r16));
#pragma unroll
                for (int nf = 0; nf < 4; nf++) {
                    int nh = nf >> 1, sel = nf & 1;
                    mma16816(acc[mf][nf], ah, bh[nh][sel], bh[nh][sel+2]);
                    mma16816(acc[mf][nf], ah, bl[nh][sel], bl[nh][sel+2]);
                    mma16816(acc[mf][nf], al, bh[nh][sel], bh[nh][sel+2]);
                }
            }
        }
    }
    int gid = lane >> 2, t4 = lane & 3;
#pragma unroll
    for (int mf = 0; mf < 4; mf++) {
#pragma unroll
        for (int nf = 0; nf < 4; nf++) {
            int co = co0 + mf*16 + gid;
            int px = px0 + pxo + nf*8 + t4*2;
            float* d = acc[mf][nf];
            float g0 = g_gate[(size_t)b*HW + px], g1 = g_gate[(size_t)b*HW + px + 1];
            float bs0 = defb[co], bs8 = defb[co+8];
            const float* yb0 = g_ybase + (size_t)(b*Cc + co  )*HW + px;
            const float* yb8 = g_ybase + (size_t)(b*Cc + co+8)*HW + px;
            *(float2*)(out + (size_t)(b*Cc + co  )*HW + px) = make_float2(
                (1.0f-g0)*yb0[0] + g0*(d[0]+bs0), (1.0f-g1)*yb0[1] + g1*(d[1]+bs0));
            *(float2*)(out + (size_t)(b*Cc + co+8)*HW + px) = make_float2(
                (1.0f-g0)*yb8[0] + g0*(d[2]+bs8), (1.0f-g1)*yb8[1] + g1*(d[3]+bs8));
        }
    }
}

__global__ void gate1x1_k(const float* __restrict__ w2, const float* __restrict__ b2) {
    int idx = blockIdx.x*blockDim.x + threadIdx.x;
    if (idx >= Bb*HW) return;
    int b = idx >> 15, p = idx & (HW-1);
    float s = b2[0];
#pragma unroll 6
    for (int c = 0; c < 66; c++)
        s = fmaf(g_gbuf[(size_t)(b*66 + c)*HW + p], w2[c], s);
    g_gate[idx] = 1.0f / (1.0f + expf(-s));
}

// ---------------- host launcher ------------------------------------------
extern "C" void kernel_launch(void* const* d_in, const int* in_sizes, int n_in,
                              void* d_out, int out_size) {
    const float* x      = (const float*)d_in[0];
    const float* off_w  = (const float*)d_in[1];
    const float* off_b  = (const float*)d_in[2];
    const float* gw1    = (const float*)d_in[3];
    const float* gb1    = (const float*)d_in[4];
    const float* gw2    = (const float*)d_in[5];
    const float* gb2    = (const float*)d_in[6];
    const float* base_w = (const float*)d_in[7];
    const float* base_b = (const float*)d_in[8];
    const float* def_w  = (const float*)d_in[9];
    const float* def_b  = (const float*)d_in[10];
    float* out = (float*)d_out;

    const int MMA_SMEM = 4*128*ASTR*2;     // 90112 bytes
    cudaFuncSetAttribute(conv_mma,     cudaFuncAttributeMaxDynamicSharedMemorySize, MMA_SMEM);
    cudaFuncSetAttribute(conv_aux_mma, cudaFuncAttributeMaxDynamicSharedMemorySize, MMA_SMEM);
    cudaFuncSetAttribute(deform_mma,   cudaFuncAttributeMaxDynamicSharedMemorySize, MMA_SMEM);

    fft_rows_k<<<Bb*Cc*Hh, 128>>>(x);
    fft_cols_k<<<Bb*KWF*64, 128>>>();
    reduce_feh_k<<<Bb*KWF, 128>>>();
    resize_fe_k<<<(Bb*HW + 255)/256, 256>>>();
    auxtail_k<<<(Bb*HW + 255)/256, 256>>>();
    transpose_k<<<dim3(HW/32, Cc/32, Bb), dim3(32, 8)>>>(x);
    wprep_k<<<(18*8192 + 255)/256, 256>>>(base_w);
    wprepD_k<<<(18*8192 + 255)/256, 256>>>(def_w);
    wprepA_k<<<(27*8192 + 255)/256, 256>>>(off_w, off_b, gw1, gb1);
    conv_mma<<<Bb*256, 256, MMA_SMEM>>>(base_b);
    conv_aux_mma<<<Bb*256, 256, MMA_SMEM>>>();
    gate1x1_k<<<(Bb*HW + 255)/256, 256>>>(gw2, gb2);
    deform_mma<<<Bb*256, 256, MMA_SMEM>>>(def_b, out);
}

// round 13
// speedup vs baseline: 2.4672x; 1.0118x over previous
#include <cuda_runtime.h>
#include <cuda_bf16.h>
#include <math.h>

#define PI_F 3.14159265358979323846f
#define Bb   2
#define Cc   128
#define Hh   128
#define Ww   256
#define HW   32768
#define AUXC 133
#define KWF  129
#define ASTR 88

__device__ float2 g_R[Bb*KWF*Cc*Hh];
__device__ float  g_part[Bb*KWF*64*128];
__device__ float  g_feh[Bb*Hh*KWF];
__device__ float  g_fe[Bb*HW];
__device__ float  g_off[Bb*18*HW];
__device__ float  g_gbuf[Bb*66*HW];
__device__ float  g_gate[Bb*HW];
__device__ float  g_ybase[Bb*Cc*HW];
__device__ float  g_xT[Bb*HW*Cc];
__device__ float  g_bF[96];
__device__ __align__(16) __nv_bfloat16 g_xbh[(size_t)Bb*HW*Cc];
__device__ __align__(16) __nv_bfloat16 g_xbl[(size_t)Bb*HW*Cc];
__device__ __align__(16) __nv_bfloat16 g_ath[(size_t)Bb*HW*16];
__device__ __align__(16) __nv_bfloat16 g_atl[(size_t)Bb*HW*16];
__device__ __align__(16) __nv_bfloat16 g_WBh[18*8192];
__device__ __align__(16) __nv_bfloat16 g_WBl[18*8192];
__device__ __align__(16) __nv_bfloat16 g_WDh[18*8192];
__device__ __align__(16) __nv_bfloat16 g_WDl[18*8192];
__device__ __align__(16) __nv_bfloat16 g_WAh[27*8192];
__device__ __align__(16) __nv_bfloat16 g_WAl[27*8192];

__device__ __forceinline__ unsigned smem_u32(const void* p){
    unsigned r;
    asm("{.reg .u64 t; cvta.to.shared.u64 t, %1; cvt.u32.u64 %0, t;}" : "=r"(r) : "l"(p));
    return r;
}
__device__ __forceinline__ void ldsm4(unsigned* r, unsigned a){
    asm volatile("ldmatrix.sync.aligned.m8n8.x4.shared.b16 {%0,%1,%2,%3}, [%4];"
        : "=r"(r[0]),"=r"(r[1]),"=r"(r[2]),"=r"(r[3]) : "r"(a));
}
__device__ __forceinline__ void mma16816(float* d, const unsigned* a, unsigned b0, unsigned b1){
    asm volatile("mma.sync.aligned.m16n8k16.row.col.f32.bf16.bf16.f32 "
        "{%0,%1,%2,%3}, {%4,%5,%6,%7}, {%8,%9}, {%0,%1,%2,%3};"
        : "+f"(d[0]),"+f"(d[1]),"+f"(d[2]),"+f"(d[3])
        : "r"(a[0]),"r"(a[1]),"r"(a[2]),"r"(a[3]), "r"(b0),"r"(b1));
}
__device__ __forceinline__ void bsplit2(float v, __nv_bfloat16& h, __nv_bfloat16& l){
    h = __float2bfloat16(v);
    l = __float2bfloat16(v - __bfloat162float(h));
}

// ---------------- FFT over W: 4 rows per 512-thread CTA ------------------
__global__ void __launch_bounds__(512) fft_rows_k(const float* __restrict__ x) {
    __shared__ float2 sm[4][256];
    __shared__ float2 tw[128];
    int tid = threadIdx.x;
    int f = tid >> 7, t = tid & 127;
    int r = blockIdx.x*4 + f;
    int m = r & (Hh-1), c = (r >> 7) & (Cc-1), b = r >> 14;
    if (tid < 128) {
        float ang = -2.0f*PI_F*(float)tid/256.0f;
        tw[tid] = make_float2(cosf(ang), sinf(ang));
    }
    const float* row = x + ((size_t)(b*Cc + c)*Hh + m)*Ww;
    for (int i = t; i < 256; i += 128)
        sm[f][__brev(i) >> 24] = make_float2(row[i], 0.0f);
    __syncthreads();
#pragma unroll
    for (int s = 1; s <= 8; s++) {
        int half = 1 << (s-1);
        int pos = t & (half-1);
        int i0 = ((t >> (s-1)) << s) | pos, i1 = i0 + half;
        float2 w = tw[pos << (8-s)];
        float2 a = sm[f][i0], bv = sm[f][i1];
        float2 tt = make_float2(bv.x*w.x - bv.y*w.y, bv.x*w.y + bv.y*w.x);
        sm[f][i0] = make_float2(a.x + tt.x, a.y + tt.y);
        sm[f][i1] = make_float2(a.x - tt.x, a.y - tt.y);
        __syncthreads();
    }
    g_R[((size_t)(b*KWF + t)*Cc + c)*Hh + m] = sm[f][t];
    if (t == 0)
        g_R[((size_t)(b*KWF + 128)*Cc + c)*Hh + m] = sm[f][128];
}

// ---------------- FFT over H: 4 channel-pairs per 512-thread CTA ---------
__global__ void __launch_bounds__(512) fft_cols_k(void) {
    __shared__ float2 sm[8][128];
    __shared__ float2 tw[64];
    __shared__ float  mg[4][128];
    int bid = blockIdx.x;
    int t16 = bid & 15;
    int kw = (bid >> 4) % KWF;
    int b  = bid / (16*KWF);
    int tid = threadIdx.x;
    int ch = tid >> 6, lane = tid & 63;
    int cp = t16*4 + (ch >> 1);
    int c  = cp*2 + (ch & 1);
    if (tid < 64) {
        float ang = -2.0f*PI_F*(float)tid/128.0f;
        tw[tid] = make_float2(cosf(ang), sinf(ang));
    }
    const float2* base = g_R + (size_t)(b*KWF + kw)*Cc*Hh + c*Hh;
#pragma unroll
    for (int i = lane; i < 128; i += 64)
        sm[ch][__brev(i) >> 25] = base[i];
    __syncthreads();
#pragma unroll
    for (int s = 1; s <= 7; s++) {
        int half = 1 << (s-1);
        int pos = lane & (half-1);
        int i0 = ((lane >> (s-1)) << s) | pos, i1 = i0 + half;
        float2 w = tw[pos << (7-s)];
        float2 a = sm[ch][i0], bv = sm[ch][i1];
        float2 t = make_float2(bv.x*w.x - bv.y*w.y, bv.x*w.y + bv.y*w.x);
        sm[ch][i0] = make_float2(a.x + t.x, a.y + t.y);
        sm[ch][i1] = make_float2(a.x - t.x, a.y - t.y);
        __syncthreads();
    }
    if ((ch & 1) == 0)
        for (int i = lane; i < 128; i += 64) {
            float2 X = sm[ch][i];
            mg[ch >> 1][i] = sqrtf(X.x*X.x + X.y*X.y);
        }
    __syncthreads();
    if ((ch & 1) == 1)
        for (int i = lane; i < 128; i += 64) {
            float2 X = sm[ch][i];
            g_part[((size_t)(b*KWF + kw)*64 + cp)*128 + i] =
                mg[ch >> 1][i] + sqrtf(X.x*X.x + X.y*X.y);
        }
}

__global__ void reduce_feh_k(void) {
    int bid = blockIdx.x;
    int kw = bid % KWF, b = bid / KWF;
    int kh = threadIdx.x;
    float s = 0.0f;
    const float* p = g_part + (size_t)bid*64*128 + kh;
#pragma unroll 8
    for (int cp = 0; cp < 64; cp++) s += p[cp*128];
    g_feh[(size_t)(b*Hh + kh)*KWF + kw] = s * (1.0f/(128.0f*sqrtf((float)HW)));
}

__global__ void resize_fe_k(void) {
    int idx = blockIdx.x*blockDim.x + threadIdx.x;
    if (idx >= Bb*HW) return;
    int w = idx & (Ww-1), h = (idx >> 8) & (Hh-1), b = idx >> 15;
    float px = ((float)w + 0.5f)*(129.0f/256.0f) - 0.5f;
    float x0f = floorf(px);
    float f = px - x0f;
    int x0 = min(max((int)x0f, 0), 128), x1 = min(max((int)x0f + 1, 0), 128);
    const float* r = g_feh + (size_t)(b*Hh + h)*KWF;
    g_fe[idx] = r[x0]*(1.0f-f) + r[x1]*f;
}

// ---------------- aux tail: 16 NHWC channels (coords, fe, pad) -----------
__global__ void auxtail_k(void) {
    int idx = blockIdx.x*blockDim.x + threadIdx.x;
    if (idx >= Bb*HW) return;
    int w = idx & (Ww-1), h = (idx >> 8) & (Hh-1);
    float th = -PI_F + (2.0f*PI_F/255.0f)*(float)w;
    float ph = -0.5f*PI_F + (PI_F/127.0f)*(float)h;
    float v[16] = {sinf(th), cosf(th), sinf(ph), cosf(ph), g_fe[idx],
                   0,0,0,0,0,0,0,0,0,0,0};
    __nv_bfloat16* oh = g_ath + (size_t)idx*16;
    __nv_bfloat16* ol = g_atl + (size_t)idx*16;
#pragma unroll
    for (int k = 0; k < 16; k++) {
        __nv_bfloat16 hb, lb; bsplit2(v[k], hb, lb);
        oh[k] = hb; ol[k] = lb;
    }
}

// ---------------- transpose + bf16 hi/lo split ---------------------------
__global__ void transpose_k(const float* __restrict__ x) {
    __shared__ float t[32][33];
    int b = blockIdx.z, p0 = blockIdx.x*32, c0 = blockIdx.y*32;
    int tx = threadIdx.x, ty = threadIdx.y;
#pragma unroll
    for (int j = 0; j < 4; j++)
        t[ty + j*8][tx] = x[(size_t)(b*Cc + c0 + ty + j*8)*HW + p0 + tx];
    __syncthreads();
#pragma unroll
    for (int j = 0; j < 4; j++) {
        float v = t[tx][ty + j*8];
        size_t o = (size_t)(b*HW + p0 + ty + j*8)*Cc + c0 + tx;
        g_xT[o] = v;
        __nv_bfloat16 hb, lb; bsplit2(v, hb, lb);
        g_xbh[o] = hb; g_xbl[o] = lb;
    }
}

// ---------------- weight preps -------------------------------------------
__global__ void wprep_k(const float* __restrict__ bw) {
    int idx = blockIdx.x*blockDim.x + threadIdx.x;
    if (idx >= 18*8192) return;
    int c = idx >> 13, r = idx & 8191;
    int co = r >> 6, k = r & 63;
    int kk = c >> 1, ci = (c & 1)*64 + k;
    float v = bw[(size_t)(co*Cc + ci)*9 + kk];
    __nv_bfloat16 hb, lb; bsplit2(v, hb, lb);
    g_WBh[idx] = hb; g_WBl[idx] = lb;
}
__global__ void wprepD_k(const float* __restrict__ dw) {
    int idx = blockIdx.x*blockDim.x + threadIdx.x;
    if (idx >= 18*8192) return;
    int c = idx >> 13, r = idx & 8191;
    int co = r >> 6, k = r & 63;
    int kk = c >> 1, ci = (c & 1)*64 + k;
    float v = dw[(size_t)(co*Cc + ci)*9 + kk];
    __nv_bfloat16 hb, lb; bsplit2(v, hb, lb);
    g_WDh[idx] = hb; g_WDl[idx] = lb;
}
__global__ void wprepA_k(const float* __restrict__ ow, const float* __restrict__ ob,
                         const float* __restrict__ gw, const float* __restrict__ gb) {
    int idx = blockIdx.x*blockDim.x + threadIdx.x;
    if (idx < 96) g_bF[idx] = (idx < 18) ? ob[idx] : (idx < 84 ? gb[idx-18] : 0.0f);
    if (idx >= 27*8192) return;
    int c = idx >> 13, r = idx & 8191;
    int co = r >> 6, k = r & 63;
    int tap = c / 3, sub = c % 3;
    int ci = sub*64 + k;
    float v = 0.0f;
    if (co < 84 && ci < AUXC)
        v = (co < 18) ? ow[(size_t)(co*AUXC + ci)*9 + tap]
                      : gw[(size_t)((co-18)*AUXC + ci)*9 + tap];
    __nv_bfloat16 hb, lb; bsplit2(v, hb, lb);
    g_WAh[idx] = hb; g_WAl[idx] = lb;
}

// ---------------- mma.sync base conv -------------------------------------
__global__ void __launch_bounds__(256) conv_mma(const float* __restrict__ bias) {
    extern __shared__ __align__(16) unsigned char dsm[];
    __nv_bfloat16* Ah = (__nv_bfloat16*)dsm;
    __nv_bfloat16* Al = Ah + 128*ASTR;
    __nv_bfloat16* Bh = Al + 128*ASTR;
    __nv_bfloat16* Bl = Bh + 128*ASTR;
    int tid = threadIdx.x;
    int wid = tid >> 5, lane = tid & 31;
    int co0 = (wid & 1)*64, pxo = (wid >> 1)*32;
    int blk = blockIdx.x;
    int b = blk >> 8;
    int px0 = (blk & 255) * 128;
    int h = px0 >> 8, w0 = px0 & 255;
    int r15 = lane & 15, r16 = (lane >> 4)*8;

    float acc[4][4][4];
#pragma unroll
    for (int mf = 0; mf < 4; mf++)
#pragma unroll
        for (int nf = 0; nf < 4; nf++)
#pragma unroll
            for (int q = 0; q < 4; q++) acc[mf][nf][q] = 0.0f;

    for (int c = 0; c < 18; c++) {
        int kk = c >> 1;
        int dy = kk/3 - 1, dx = kk%3 - 1;
        int ci0 = (c & 1)*64;
        __syncthreads();
        for (int i = tid; i < 2048; i += 256) {
            int buf = i >> 10, idx = i & 1023;
            int row = idx >> 3, seg = idx & 7;
            *((float4*)((buf ? Al : Ah) + row*ASTR) + seg) =
                *((const float4*)((buf ? g_WBl : g_WBh) + (size_t)c*8192 + row*64) + seg);
        }
        int sh = h + dy;
        for (int i = tid; i < 2048; i += 256) {
            int buf = i >> 10, idx = i & 1023;
            int p = idx >> 3, seg = idx & 7;
            int sw = w0 + p + dx;
            float4 v = make_float4(0.f,0.f,0.f,0.f);
            if (sw >= 0 && sw < Ww && sh >= 0 && sh < Hh)
                v = *((const float4*)((buf ? g_xbl : g_xbh) +
                      ((size_t)(b*HW) + sh*Ww + sw)*Cc + ci0) + seg);
            *((float4*)((buf ? Bl : Bh) + p*ASTR) + seg) = v;
        }
        __syncthreads();
#pragma unroll
        for (int ks = 0; ks < 4; ks++) {
            unsigned bh[2][4], bl[2][4];
#pragma unroll
            for (int nh = 0; nh < 2; nh++) {
                ldsm4(bh[nh], smem_u32(Bh + (pxo + nh*16 + r15)*ASTR + ks*16 + r16));
                ldsm4(bl[nh], smem_u32(Bl + (pxo + nh*16 + r15)*ASTR + ks*16 + r16));
            }
#pragma unroll
            for (int mf = 0; mf < 4; mf++) {
                unsigned ah[4], al[4];
                ldsm4(ah, smem_u32(Ah + (co0 + mf*16 + r15)*ASTR + ks*16 + r16));
                ldsm4(al, smem_u32(Al + (co0 + mf*16 + r15)*ASTR + ks*16 + r16));
#pragma unroll
                for (int nf = 0; nf < 4; nf++) {
                    int nh = nf >> 1, sel = nf & 1;
                    mma16816(acc[mf][nf], ah, bh[nh][sel], bh[nh][sel+2]);
                    mma16816(acc[mf][nf], ah, bl[nh][sel], bl[nh][sel+2]);
                    mma16816(acc[mf][nf], al, bh[nh][sel], bh[nh][sel+2]);
                }
            }
        }
    }
    int gid = lane >> 2, t4 = lane & 3;
#pragma unroll
    for (int mf = 0; mf < 4; mf++) {
#pragma unroll
        for (int nf = 0; nf < 4; nf++) {
            int co = co0 + mf*16 + gid;
            int px = px0 + pxo + nf*8 + t4*2;
            float* d = acc[mf][nf];
            *(float2*)(g_ybase + (size_t)(b*Cc + co  )*HW + px) =
                make_float2(d[0] + bias[co],   d[1] + bias[co]);
            *(float2*)(g_ybase + (size_t)(b*Cc + co+8)*HW + px) =
                make_float2(d[2] + bias[co+8], d[3] + bias[co+8]);
        }
    }
}

// ---------------- mma.sync aux conv (offset+gate) ------------------------
__global__ void __launch_bounds__(256) conv_aux_mma(void) {
    extern __shared__ __align__(16) unsigned char dsm[];
    __nv_bfloat16* Ah = (__nv_bfloat16*)dsm;
    __nv_bfloat16* Al = Ah + 128*ASTR;
    __nv_bfloat16* Bh = Al + 128*ASTR;
    __nv_bfloat16* Bl = Bh + 128*ASTR;
    int tid = threadIdx.x;
    int wid = tid >> 5, lane = tid & 31;
    int co0 = (wid & 1)*64, pxo = (wid >> 1)*32;
    int blk = blockIdx.x;
    int b = blk >> 8;
    int px0 = (blk & 255) * 128;
    int h = px0 >> 8, w0 = px0 & 255;
    int r15 = lane & 15, r16 = (lane >> 4)*8;

    float acc[4][4][4];
#pragma unroll
    for (int mf = 0; mf < 4; mf++)
#pragma unroll
        for (int nf = 0; nf < 4; nf++)
#pragma unroll
            for (int q = 0; q < 4; q++) acc[mf][nf][q] = 0.0f;

    for (int c = 0; c < 27; c++) {
        int tap = c / 3, sub = c - tap*3;
        int dy = tap/3 - 1, dx = tap%3 - 1;
        __syncthreads();
        for (int i = tid; i < 2048; i += 256) {
            int buf = i >> 10, idx = i & 1023;
            int row = idx >> 3, seg = idx & 7;
            *((float4*)((buf ? Al : Ah) + row*ASTR) + seg) =
                *((const float4*)((buf ? g_WAl : g_WAh) + (size_t)c*8192 + row*64) + seg);
        }
        int sh = h + dy;
        if (sub < 2) {
            int ci0 = sub*64;
            for (int i = tid; i < 2048; i += 256) {
                int buf = i >> 10, idx = i & 1023;
                int p = idx >> 3, seg = idx & 7;
                int sw = w0 + p + dx;
                float4 v = make_float4(0.f,0.f,0.f,0.f);
                if (sw >= 0 && sw < Ww && sh >= 0 && sh < Hh)
                    v = *((const float4*)((buf ? g_xbl : g_xbh) +
                          ((size_t)(b*HW) + sh*Ww + sw)*Cc + ci0) + seg);
                *((float4*)((buf ? Bl : Bh) + p*ASTR) + seg) = v;
            }
        } else {
            for (int i = tid; i < 512; i += 256) {
                int buf = i >> 8, idx = i & 255;
                int p = idx >> 1, seg = idx & 1;
                int sw = w0 + p + dx;
                float4 v = make_float4(0.f,0.f,0.f,0.f);
                if (sw >= 0 && sw < Ww && sh >= 0 && sh < Hh)
                    v = *((const float4*)((buf ? g_atl : g_ath) +
                          ((size_t)(b*HW) + sh*Ww + sw)*16) + seg);
                *((float4*)((buf ? Bl : Bh) + p*ASTR) + seg) = v;
            }
        }
        __syncthreads();
        int nks = (sub < 2) ? 4 : 1;
        for (int ks = 0; ks < nks; ks++) {
            unsigned bh[2][4], bl[2][4];
#pragma unroll
            for (int nh = 0; nh < 2; nh++) {
                ldsm4(bh[nh], smem_u32(Bh + (pxo + nh*16 + r15)*ASTR + ks*16 + r16));
                ldsm4(bl[nh], smem_u32(Bl + (pxo + nh*16 + r15)*ASTR + ks*16 + r16));
            }
#pragma unroll
            for (int mf = 0; mf < 4; mf++) {
                unsigned ah[4], al[4];
                ldsm4(ah, smem_u32(Ah + (co0 + mf*16 + r15)*ASTR + ks*16 + r16));
                ldsm4(al, smem_u32(Al + (co0 + mf*16 + r15)*ASTR + ks*16 + r16));
#pragma unroll
                for (int nf = 0; nf < 4; nf++) {
                    int nh = nf >> 1, sel = nf & 1;
                    mma16816(acc[mf][nf], ah, bh[nh][sel], bh[nh][sel+2]);
                    mma16816(acc[mf][nf], ah, bl[nh][sel], bl[nh][sel+2]);
                    mma16816(acc[mf][nf], al, bh[nh][sel], bh[nh][sel+2]);
                }
            }
        }
    }
    int gid = lane >> 2, t4 = lane & 3;
#pragma unroll
    for (int mf = 0; mf < 4; mf++) {
#pragma unroll
        for (int nf = 0; nf < 4; nf++) {
            int px = px0 + pxo + nf*8 + t4*2;
            float* d = acc[mf][nf];
#pragma unroll
            for (int half = 0; half < 2; half++) {
                int co = co0 + mf*16 + gid + half*8;
                float v0 = d[half*2] + g_bF[co], v1 = d[half*2+1] + g_bF[co];
                if (co < 18) {
                    *(float2*)(g_off + (size_t)(b*18 + co)*HW + px) = make_float2(v0, v1);
                } else if (co < 84) {
                    *(float2*)(g_gbuf + (size_t)(b*66 + co - 18)*HW + px) =
                        make_float2(fmaxf(v0, 0.0f), fmaxf(v1, 0.0f));
                }
            }
        }
    }
}

// ---------------- mma.sync deform GEMM + blend ---------------------------
__global__ void __launch_bounds__(256) deform_mma(
        const float* __restrict__ defb, float* __restrict__ out) {
    extern __shared__ __align__(16) unsigned char dsm[];
    __nv_bfloat16* Ah = (__nv_bfloat16*)dsm;
    __nv_bfloat16* Al = Ah + 128*ASTR;
    __nv_bfloat16* Bh = Al + 128*ASTR;
    __nv_bfloat16* Bl = Bh + 128*ASTR;
    __shared__ int   sC[4][128];
    __shared__ float sWt[4][128];
    int tid = threadIdx.x;
    int wid = tid >> 5, lane = tid & 31;
    int co0 = (wid & 1)*64, pxo = (wid >> 1)*32;
    int blk = blockIdx.x;
    int b = blk >> 8;
    int px0 = (blk & 255) * 128;
    int r15 = lane & 15, r16 = (lane >> 4)*8;

    float acc[4][4][4];
#pragma unroll
    for (int mf = 0; mf < 4; mf++)
#pragma unroll
        for (int nf = 0; nf < 4; nf++)
#pragma unroll
            for (int q = 0; q < 4; q++) acc[mf][nf][q] = 0.0f;

    for (int c = 0; c < 18; c++) {
        int kk = c >> 1;
        int ci0 = (c & 1)*64;
        __syncthreads();
        if ((c & 1) == 0 && tid < 128) {
            int pp = px0 + tid;
            int hh = pp >> 8, ww = pp & (Ww-1);
            float fpx = (float)ww + g_off[(size_t)(b*18 + 2*kk    )*HW + pp];
            float fpy = (float)hh + g_off[(size_t)(b*18 + 2*kk + 1)*HW + pp];
            float fx0 = floorf(fpx), fy0 = floorf(fpy);
            int X0 = (int)fx0, Y0 = (int)fy0;
            float fx = fpx - fx0, fy = fpy - fy0;
            float w00 = (1.0f-fx)*(1.0f-fy), w10 = fx*(1.0f-fy);
            float w01 = (1.0f-fx)*fy,        w11 = fx*fy;
            if (X0   < 0 || X0   >= Ww) { w00 = 0.0f; w01 = 0.0f; }
            if (X0+1 < 0 || X0+1 >= Ww) { w10 = 0.0f; w11 = 0.0f; }
            if (Y0   < 0 || Y0   >= Hh) { w00 = 0.0f; w10 = 0.0f; }
            if (Y0+1 < 0 || Y0+1 >= Hh) { w01 = 0.0f; w11 = 0.0f; }
            sC[0][tid] = min(max(X0,   0), Ww-1);
            sC[1][tid] = min(max(X0+1, 0), Ww-1);
            sC[2][tid] = min(max(Y0,   0), Hh-1);
            sC[3][tid] = min(max(Y0+1, 0), Hh-1);
            sWt[0][tid] = w00; sWt[1][tid] = w10; sWt[2][tid] = w01; sWt[3][tid] = w11;
        }
        __syncthreads();
        for (int i = tid; i < 2048; i += 256) {
            int buf = i >> 10, idx = i & 1023;
            int row = idx >> 3, seg = idx & 7;
            *((float4*)((buf ? Al : Ah) + row*ASTR) + seg) =
                *((const float4*)((buf ? g_WDl : g_WDh) + (size_t)c*8192 + row*64) + seg);
        }
        for (int i = tid; i < 2048; i += 256) {
            int p = i >> 4, g = i & 15;
            int cx0 = sC[0][p], cx1 = sC[1][p], cy0 = sC[2][p], cy1 = sC[3][p];
            float w00 = sWt[0][p], w10 = sWt[1][p], w01 = sWt[2][p], w11 = sWt[3][p];
            size_t base = (size_t)(b*HW)*Cc + (size_t)(ci0 + g*4);
            float4 a00 = *(const float4*)(g_xT + base + (size_t)(cy0*Ww + cx0)*Cc);
            float4 a10 = *(const float4*)(g_xT + base + (size_t)(cy0*Ww + cx1)*Cc);
            float4 a01 = *(const float4*)(g_xT + base + (size_t)(cy1*Ww + cx0)*Cc);
            float4 a11 = *(const float4*)(g_xT + base + (size_t)(cy1*Ww + cx1)*Cc);
            float4 r;
            r.x = w00*a00.x + w10*a10.x + w01*a01.x + w11*a11.x;
            r.y = w00*a00.y + w10*a10.y + w01*a01.y + w11*a11.y;
            r.z = w00*a00.z + w10*a10.z + w01*a01.z + w11*a11.z;
            r.w = w00*a00.w + w10*a10.w + w01*a01.w + w11*a11.w;
            __nv_bfloat16 h0, l0, h1, l1, h2, l2, h3, l3;
            bsplit2(r.x, h0, l0); bsplit2(r.y, h1, l1);
            bsplit2(r.z, h2, l2); bsplit2(r.w, h3, l3);
            __nv_bfloat162* dh = (__nv_bfloat162*)(Bh + p*ASTR + g*4);
            dh[0] = __nv_bfloat162(h0, h1); dh[1] = __nv_bfloat162(h2, h3);
            __nv_bfloat162* dl = (__nv_bfloat162*)(Bl + p*ASTR + g*4);
            dl[0] = __nv_bfloat162(l0, l1); dl[1] = __nv_bfloat162(l2, l3);
        }
        __syncthreads();
#pragma unroll
        for (int ks = 0; ks < 4; ks++) {
            unsigned bh[2][4], bl[2][4];
#pragma unroll
            for (int nh = 0; nh < 2; nh++) {
                ldsm4(bh[nh], smem_u32(Bh + (pxo + nh*16 + r15)*ASTR + ks*16 + r16));
                ldsm4(bl[nh], smem_u32(Bl + (pxo + nh*16 + r15)*ASTR + ks*16 + r16));
            }
#pragma unroll
            for (int mf = 0; mf < 4; mf++) {
                unsigned ah[4], al[4];
                ldsm4(ah, smem_u32(Ah + (co0 + mf*16 + r15)*ASTR + ks*16 + r16));
                ldsm4(al, smem_u32(Al + (co0 + mf*16 + r15)*ASTR + ks*16 + r16));
#pragma unroll
                for (int nf = 0; nf < 4; nf++) {
                    int nh = nf >> 1, sel = nf & 1;
                    mma16816(acc[mf][nf], ah, bh[nh][sel], bh[nh][sel+2]);
                    mma16816(acc[mf][nf], ah, bl[nh][sel], bl[nh][sel+2]);
                    mma16816(acc[mf][nf], al, bh[nh][sel], bh[nh][sel+2]);
                }
            }
        }
    }
    int gid = lane >> 2, t4 = lane & 3;
#pragma unroll
    for (int mf = 0; mf < 4; mf++) {
#pragma unroll
        for (int nf = 0; nf < 4; nf++) {
            int co = co0 + mf*16 + gid;
            int px = px0 + pxo + nf*8 + t4*2;
            float* d = acc[mf][nf];
            float g0 = g_gate[(size_t)b*HW + px], g1 = g_gate[(size_t)b*HW + px + 1];
            float bs0 = defb[co], bs8 = defb[co+8];
            const float* yb0 = g_ybase + (size_t)(b*Cc + co  )*HW + px;
            const float* yb8 = g_ybase + (size_t)(b*Cc + co+8)*HW + px;
            *(float2*)(out + (size_t)(b*Cc + co  )*HW + px) = make_float2(
                (1.0f-g0)*yb0[0] + g0*(d[0]+bs0), (1.0f-g1)*yb0[1] + g1*(d[1]+bs0));
            *(float2*)(out + (size_t)(b*Cc + co+8)*HW + px) = make_float2(
                (1.0f-g0)*yb8[0] + g0*(d[2]+bs8), (1.0f-g1)*yb8[1] + g1*(d[3]+bs8));
        }
    }
}

__global__ void gate1x1_k(const float* __restrict__ w2, const float* __restrict__ b2) {
    int idx = blockIdx.x*blockDim.x + threadIdx.x;
    if (idx >= Bb*HW) return;
    int b = idx >> 15, p = idx & (HW-1);
    float s = b2[0];
#pragma unroll 6
    for (int c = 0; c < 66; c++)
        s = fmaf(g_gbuf[(size_t)(b*66 + c)*HW + p], w2[c], s);
    g_gate[idx] = 1.0f / (1.0f + expf(-s));
}

// ---------------- host launcher ------------------------------------------
extern "C" void kernel_launch(void* const* d_in, const int* in_sizes, int n_in,
                              void* d_out, int out_size) {
    const float* x      = (const float*)d_in[0];
    const float* off_w  = (const float*)d_in[1];
    const float* off_b  = (const float*)d_in[2];
    const float* gw1    = (const float*)d_in[3];
    const float* gb1    = (const float*)d_in[4];
    const float* gw2    = (const float*)d_in[5];
    const float* gb2    = (const float*)d_in[6];
    const float* base_w = (const float*)d_in[7];
    const float* base_b = (const float*)d_in[8];
    const float* def_w  = (const float*)d_in[9];
    const float* def_b  = (const float*)d_in[10];
    float* out = (float*)d_out;

    const int MMA_SMEM = 4*128*ASTR*2;     // 90112 bytes
    cudaFuncSetAttribute(conv_mma,     cudaFuncAttributeMaxDynamicSharedMemorySize, MMA_SMEM);
    cudaFuncSetAttribute(conv_aux_mma, cudaFuncAttributeMaxDynamicSharedMemorySize, MMA_SMEM);
    cudaFuncSetAttribute(deform_mma,   cudaFuncAttributeMaxDynamicSharedMemorySize, MMA_SMEM);

    fft_rows_k<<<Bb*Cc*Hh/4, 512>>>(x);
    fft_cols_k<<<Bb*KWF*16, 512>>>();
    reduce_feh_k<<<Bb*KWF, 128>>>();
    resize_fe_k<<<(Bb*HW + 255)/256, 256>>>();
    auxtail_k<<<(Bb*HW + 255)/256, 256>>>();
    transpose_k<<<dim3(HW/32, Cc/32, Bb), dim3(32, 8)>>>(x);
    wprep_k<<<(18*8192 + 255)/256, 256>>>(base_w);
    wprepD_k<<<(18*8192 + 255)/256, 256>>>(def_w);
    wprepA_k<<<(27*8192 + 255)/256, 256>>>(off_w, off_b, gw1, gb1);
    conv_mma<<<Bb*256, 256, MMA_SMEM>>>(base_b);
    conv_aux_mma<<<Bb*256, 256, MMA_SMEM>>>();
    gate1x1_k<<<(Bb*HW + 255)/256, 256>>>(gw2, gb2);
    deform_mma<<<Bb*256, 256, MMA_SMEM>>>(def_b, out);
}